// round 14
// baseline (speedup 1.0000x reference)
#include <cuda_runtime.h>
#include <cuda_fp16.h>
#include <cstdint>

#define N_NODES 100000
#define N_EDGES 500000
#define HID 128
#define OUTD 349
#define NET 8
#define BN_EPS 1e-5f
#define MTILE 64
#define NTILES_M ((N_NODES + MTILE - 1) / MTILE)  // 1563
#define NSCAN1 ((N_NODES + 1023) / 1024)          // 98

// ---------------- scratch (static device globals; no allocation) ----------
__device__ float g_h[N_NODES * HID];     // input-linear output (residual source)
__device__ float g_x[N_NODES * HID];     // conv0 out + residual (BN input)
__device__ float g_deg0[N_NODES], g_deg1[N_NODES];
__device__ int   g_count[N_NODES];
__device__ int   g_csroff[N_NODES + 1];
__device__ int   g_cursor[N_NODES];
__device__ int   g_bsum[NSCAN1];
__device__ int   g_csrsrc[N_EDGES];
__device__ float g_csrw0[N_EDGES], g_csrw1[N_EDGES];
__device__ float g_rws[2 * NET];
__device__ float g_sum[HID], g_sumsq[HID];
__device__ int   g_cnt[2];
__device__ int   g_list0[N_NODES], g_list1[N_NODES];

// fp16 hi/lo weight images, layout [tile][k=128][n=128] row-major
__device__ __half g_wI0h[16384], g_wI0l[16384];       // lin0_w
__device__ __half g_wI1h[16384], g_wI1l[16384];       // lin1_w
__device__ __half g_wC0h[16384], g_wC0l[16384];       // conv0_w
__device__ __half g_wC1h[3 * 16384], g_wC1l[3 * 16384];  // conv1_w (3 tiles)

// ---------------- mma.sync GEMM machinery ----------------------------------
// A in fp16 (truncated), W split hi+lo fp16 -> 2 mma terms. 512 threads/CTA.
#define ROWB 272                    // 136 fp16 padded row (conflict-free LDSM)
#define OFF_A    0                  // 64 x 272 = 17408
#define OFF_B_HI 17408              // 128 x 272 = 34816
#define OFF_B_LO 52224
#define SMEM_MMA 87040              // 85KB -> 2 CTAs/SM

__device__ __forceinline__ uint32_t smem_u32(const void* p) {
    uint32_t a;
    asm("{ .reg .u64 t; cvta.to.shared.u64 t, %1; cvt.u32.u64 %0, t; }"
        : "=r"(a) : "l"(p));
    return a;
}

__device__ __forceinline__ void ldsm4(uint32_t addr, uint32_t* r) {
    asm volatile("ldmatrix.sync.aligned.m8n8.x4.shared.b16 {%0,%1,%2,%3}, [%4];"
                 : "=r"(r[0]), "=r"(r[1]), "=r"(r[2]), "=r"(r[3]) : "r"(addr));
}
__device__ __forceinline__ void ldsm2t(uint32_t addr, uint32_t* r) {
    asm volatile("ldmatrix.sync.aligned.m8n8.x2.trans.shared.b16 {%0,%1}, [%2];"
                 : "=r"(r[0]), "=r"(r[1]) : "r"(addr));
}
__device__ __forceinline__ void mma16816(float* d, const uint32_t* a, const uint32_t* b) {
    asm volatile(
        "mma.sync.aligned.m16n8k16.row.col.f32.f16.f16.f32 "
        "{%0,%1,%2,%3}, {%4,%5,%6,%7}, {%8,%9}, {%0,%1,%2,%3};"
        : "+f"(d[0]), "+f"(d[1]), "+f"(d[2]), "+f"(d[3])
        : "r"(a[0]), "r"(a[1]), "r"(a[2]), "r"(a[3]), "r"(b[0]), "r"(b[1]));
}

// write 16 fp32 (one eighth-row) as packed fp16 into the A tile
__device__ __forceinline__ void stage_write16(char* smem, int row, int oct,
                                              const float* a) {
    uint32_t off = (uint32_t)row * ROWB + oct * 32;
#pragma unroll
    for (int g = 0; g < 2; g++) {
        uint32_t p[4];
#pragma unroll
        for (int i = 0; i < 4; i++)
            asm("cvt.rn.f16x2.f32 %0, %1, %2;"
                : "=r"(p[i]) : "f"(a[g * 8 + 2 * i + 1]), "f"(a[g * 8 + 2 * i]));
        *reinterpret_cast<uint4*>(smem + OFF_A + off + g * 16) =
            make_uint4(p[0], p[1], p[2], p[3]);
    }
}

// stage 16 fp32 (eighth row) from a contiguous source row
__device__ __forceinline__ void stage_plain16(char* smem, int row, int oct,
                                              const float* src) {
    float f[16];
    if (src) {
#pragma unroll
        for (int g = 0; g < 4; g++) {
            float4 v = ((const float4*)src)[g];
            f[g * 4 + 0] = v.x; f[g * 4 + 1] = v.y;
            f[g * 4 + 2] = v.z; f[g * 4 + 3] = v.w;
        }
    } else {
#pragma unroll
        for (int i = 0; i < 16; i++) f[i] = 0.f;
    }
    stage_write16(smem, row, oct, f);
}

// gather-aggregate an eighth row over incoming edges
__device__ __forceinline__ void stage_gather16(char* smem, int row, int oct, int gr,
                                               const float* srcbase,
                                               const float* warr) {
    float a[16];
#pragma unroll
    for (int i = 0; i < 16; i++) a[i] = 0.f;
    if (gr < N_NODES) {
        int s0 = g_csroff[gr], s1 = g_csroff[gr + 1];
#pragma unroll 2
        for (int e = s0; e < s1; e++) {
            int src = g_csrsrc[e];
            float w = warr[e];
            const float4* p = (const float4*)(srcbase + (size_t)src * HID + oct * 16);
#pragma unroll
            for (int g = 0; g < 4; g++) {
                float4 v = __ldg(&p[g]);
                a[g * 4 + 0] += w * v.x; a[g * 4 + 1] += w * v.y;
                a[g * 4 + 2] += w * v.z; a[g * 4 + 3] += w * v.w;
            }
        }
    }
    stage_write16(smem, row, oct, a);
}

// gather with fused bn+prelu on source values (layer 1); sc/sh read from smem
__device__ __forceinline__ void stage_gather_bn16(char* smem, int row, int oct,
                                                  int gr, const float* ssc,
                                                  const float* ssh, float pa) {
    float a[16];
#pragma unroll
    for (int i = 0; i < 16; i++) a[i] = 0.f;
    if (gr < N_NODES) {
        int s0 = g_csroff[gr], s1 = g_csroff[gr + 1];
        const float4* sc4 = (const float4*)(ssc + oct * 16);
        const float4* sh4 = (const float4*)(ssh + oct * 16);
#pragma unroll 2
        for (int e = s0; e < s1; e++) {
            int src = g_csrsrc[e];
            float w = g_csrw1[e];
            const float4* p = (const float4*)(g_x + (size_t)src * HID + oct * 16);
#pragma unroll
            for (int g = 0; g < 4; g++) {
                float4 v = __ldg(&p[g]);
                float4 sc = sc4[g], sh = sh4[g];  // smem broadcast loads
                float z0 = v.x * sc.x + sh.x;
                float z1 = v.y * sc.y + sh.y;
                float z2 = v.z * sc.z + sh.z;
                float z3 = v.w * sc.w + sh.w;
                z0 = (z0 >= 0.f) ? z0 : pa * z0;
                z1 = (z1 >= 0.f) ? z1 : pa * z1;
                z2 = (z2 >= 0.f) ? z2 : pa * z2;
                z3 = (z3 >= 0.f) ? z3 : pa * z3;
                a[g * 4 + 0] += w * z0; a[g * 4 + 1] += w * z1;
                a[g * 4 + 2] += w * z2; a[g * 4 + 3] += w * z3;
            }
        }
    }
    stage_write16(smem, row, oct, a);
}

// copy one pre-split B tile (hi/lo [k][n] images) into padded smem rows
__device__ __forceinline__ void stage_b(char* smem, const __half* bh,
                                        const __half* bl, int tid) {
    const uint4* h4 = (const uint4*)bh;
    const uint4* l4 = (const uint4*)bl;
    for (int i = tid; i < 2048; i += 512) {
        int k = i >> 4, s = i & 15;
        *(uint4*)(smem + OFF_B_HI + k * ROWB + s * 16) = h4[i];
        *(uint4*)(smem + OFF_B_LO + k * ROWB + s * 16) = l4[i];
    }
}

// core: 16 warps; warp (wm=w&1, wn=w>>1 in 0..7): rows wm*32..+31, cols wn*16..+15
__device__ __forceinline__ void mma_core(uint32_t sb, float acc[4][4]) {
    int lane = threadIdx.x & 31;
    int w = threadIdx.x >> 5;
    int wm = w & 1, wn = w >> 1;
    uint32_t aaddr[2], baddr[2];
#pragma unroll
    for (int mt = 0; mt < 2; mt++)
        aaddr[mt] = sb + OFF_A +
                    (uint32_t)(wm * 32 + mt * 16 + (lane & 15)) * ROWB +
                    (lane >> 4) * 16;
#pragma unroll
    for (int nt = 0; nt < 2; nt++)
        baddr[nt] = sb + OFF_B_HI + (uint32_t)(lane & 15) * ROWB +
                    (wn * 16 + nt * 8) * 2;
#pragma unroll
    for (int ks = 0; ks < 8; ks++) {
        uint32_t bh[2][2], bl[2][2];
#pragma unroll
        for (int nt = 0; nt < 2; nt++) {
            uint32_t ba = baddr[nt] + ks * (16 * ROWB);
            ldsm2t(ba, bh[nt]);
            ldsm2t(ba + (OFF_B_LO - OFF_B_HI), bl[nt]);
        }
#pragma unroll
        for (int mt = 0; mt < 2; mt++) {
            uint32_t ah[4];
            ldsm4(aaddr[mt] + ks * 32, ah);
#pragma unroll
            for (int nt = 0; nt < 2; nt++) {
                mma16816(acc[mt * 2 + nt], ah, bh[nt]);
                mma16816(acc[mt * 2 + nt], ah, bl[nt]);
            }
        }
    }
}

// ---------------- prep ----------------------------------------------------
// zero/init + relation weights + ALL weight hi/lo images in one launch
__global__ void k_init(const float* __restrict__ rw0, const float* __restrict__ rw1,
                       const float* __restrict__ lin0_w,
                       const float* __restrict__ lin1_w,
                       const float* __restrict__ conv0_w,
                       const float* __restrict__ conv1_w) {
    int i = blockIdx.x * blockDim.x + threadIdx.x;
    if (i < N_NODES) { g_deg0[i] = 0.0f; g_deg1[i] = 0.0f; g_count[i] = 0; }
    if (i < HID)     { g_sum[i] = 0.0f;  g_sumsq[i] = 0.0f; }
    if (i < 2)       { g_cnt[i] = 0; }
    if (i < NET) {
        float v = rw0[i] * 100.0f;
        g_rws[i] = (v >= 0.0f) ? v : 0.01f * v;
    } else if (i < 2 * NET) {
        float v = rw1[i - NET] * 100.0f;
        g_rws[i] = (v >= 0.0f) ? v : 0.01f * v;
    }
    if (i < 6 * 16384) {
        int img = i >> 14;
        int rem = i & 16383;
        int k = rem >> 7, n = rem & 127;
        const float* W;
        int ncols, col, off;
        __half *hi, *lo;
        if (img == 0)      { W = lin0_w;  ncols = HID;  col = n; hi = g_wI0h; lo = g_wI0l; off = rem; }
        else if (img == 1) { W = lin1_w;  ncols = HID;  col = n; hi = g_wI1h; lo = g_wI1l; off = rem; }
        else if (img == 2) { W = conv0_w; ncols = HID;  col = n; hi = g_wC0h; lo = g_wC0l; off = rem; }
        else { int t = img - 3; W = conv1_w; ncols = OUTD; col = t * 128 + n;
               hi = g_wC1h; lo = g_wC1l; off = t * 16384 + rem; }
        float v = (col < ncols) ? W[(size_t)k * ncols + col] : 0.f;
        __half h = __float2half_rn(v);
        hi[off] = h;
        lo[off] = __float2half_rn(v - __half2float(h));
    }
}

// partition (warp-aggregated) + degree/count accumulation in one launch
__global__ void k_part_deg(const int* __restrict__ ntype,
                           const int* __restrict__ ei,
                           const int* __restrict__ et) {
    int i = blockIdx.x * blockDim.x + threadIdx.x;
    int lane = threadIdx.x & 31;
    int t = (i < N_NODES) ? ntype[i] : -1;
#pragma unroll
    for (int tt = 0; tt < 2; tt++) {
        unsigned m = __ballot_sync(0xffffffffu, t == tt);
        if (t == tt) {
            int leader = __ffs(m) - 1;
            int pos = 0;
            if (lane == leader) pos = atomicAdd(&g_cnt[tt], __popc(m));
            pos = __shfl_sync(m, pos, leader);
            pos += __popc(m & ((1u << lane) - 1u));
            if (tt == 0) g_list0[pos] = i; else g_list1[pos] = i;
        }
    }
    if (i < N_EDGES) {
        int c = ei[N_EDGES + i];
        int ty = et[i];
        atomicAdd(&g_deg0[c], g_rws[ty]);
        atomicAdd(&g_deg1[c], g_rws[NET + ty]);
        atomicAdd(&g_count[c], 1);
    }
}

// phase 1 of scan: per-1024-block exclusive scan + block sums
__global__ __launch_bounds__(1024) void k_scan1() {
    __shared__ int s[1024];
    int tid = threadIdx.x;
    int i = blockIdx.x * 1024 + tid;
    int v = (i < N_NODES) ? g_count[i] : 0;
    s[tid] = v;
    __syncthreads();
#pragma unroll
    for (int d = 1; d < 1024; d <<= 1) {
        int t = (tid >= d) ? s[tid - d] : 0;
        __syncthreads();
        s[tid] += t;
        __syncthreads();
    }
    if (i < N_NODES) g_csroff[i] = s[tid] - v;
    if (tid == 1023) g_bsum[blockIdx.x] = s[1023];
}

// phase 2+3 merged: each block redundantly scans the 98 block sums, then
// applies the prefix to its 256 csroff entries.
__global__ __launch_bounds__(256) void k_scan23() {
    __shared__ int wsum[4];
    __shared__ int ex[128];
    int tid = threadIdx.x, lane = tid & 31, wid = tid >> 5;
    int v = 0, x = 0;
    if (tid < 128) {
        v = (tid < NSCAN1) ? g_bsum[tid] : 0;
        x = v;
#pragma unroll
        for (int d = 1; d < 32; d <<= 1) {
            int t = __shfl_up_sync(0xffffffffu, x, d);
            if (lane >= d) x += t;
        }
        if (lane == 31) wsum[wid] = x;
    }
    __syncthreads();
    if (tid < 128) {
        int base = 0;
#pragma unroll
        for (int k = 0; k < 4; k++) base += (k < wid) ? wsum[k] : 0;
        ex[tid] = base + x - v;  // exclusive prefix of block sums
    }
    __syncthreads();
    int i = blockIdx.x * blockDim.x + tid;
    if (i < N_NODES) {
        int o = g_csroff[i] + ex[i >> 10];
        g_csroff[i] = o;
        g_cursor[i] = o;
    }
    if (i == 0) g_csroff[N_NODES] = N_EDGES;
}

__global__ void k_fill(const int* __restrict__ ei, const int* __restrict__ et) {
    int e = blockIdx.x * blockDim.x + threadIdx.x;
    if (e >= N_EDGES) return;
    int r = ei[e];
    int c = ei[N_EDGES + e];
    int t = et[e];
    int pos = atomicAdd(&g_cursor[c], 1);
    g_csrsrc[pos] = r;
    g_csrw0[pos] = g_rws[t] / fabsf(g_deg0[c]);
    g_csrw1[pos] = g_rws[NET + t] / fabsf(g_deg1[c]);
}

// ---------------- mma GEMM kernels (512 threads) ---------------------------

// both input linears in ONE launch: blocks [0, nt0) do type 0, rest type 1
__global__ __launch_bounds__(512, 2) void k_mma_input(
    const float* __restrict__ x0, const float* __restrict__ x1,
    const int* __restrict__ lidx,
    const float* __restrict__ b0, const float* __restrict__ b1) {
    const int cnt0 = g_cnt[0], cnt1 = g_cnt[1];
    const int nt0 = (cnt0 + MTILE - 1) / MTILE;
    int pass, tile;
    if ((int)blockIdx.x < nt0) { pass = 0; tile = blockIdx.x; }
    else { pass = 1; tile = blockIdx.x - nt0; }
    const int cnt = pass ? cnt1 : cnt0;
    const int m0 = tile * MTILE;
    if (m0 >= cnt) return;
    const int* list = pass ? g_list1 : g_list0;
    const float* xk = pass ? x1 : x0;
    const float* b = pass ? b1 : b0;
    extern __shared__ char smem[];
    int tid = threadIdx.x;

    stage_b(smem, pass ? g_wI1h : g_wI0h, pass ? g_wI1l : g_wI0l, tid);
    {
        int row = tid >> 3, oct = tid & 7;
        int lr = m0 + row;
        const float* src = nullptr;
        if (lr < cnt) src = xk + (size_t)lidx[list[lr]] * HID + oct * 16;
        stage_plain16(smem, row, oct, src);
    }
    __syncthreads();

    float acc[4][4] = {};
    mma_core(smem_u32(smem), acc);

    int lane = tid & 31, w = tid >> 5, wm = w & 1, wn = w >> 1;
#pragma unroll
    for (int mt = 0; mt < 2; mt++)
#pragma unroll
        for (int half = 0; half < 2; half++) {
            int lr = m0 + wm * 32 + mt * 16 + (lane >> 2) + half * 8;
            if (lr >= cnt) continue;
            float* dst = g_h + (size_t)list[lr] * HID;
#pragma unroll
            for (int nt = 0; nt < 2; nt++) {
                int c = wn * 16 + nt * 8 + (lane & 3) * 2;
                float2 bb = *(const float2*)(b + c);
                float2 o = {acc[mt * 2 + nt][half * 2 + 0] + bb.x,
                            acc[mt * 2 + nt][half * 2 + 1] + bb.y};
                *(float2*)(dst + c) = o;
            }
        }
}

// g_x = gather(h) @ conv0_w + b + g_h ; BN stats fused in epilogue
__global__ __launch_bounds__(512, 2) void k_mma_gemm0(const float* __restrict__ b) {
    const int m0 = blockIdx.x * MTILE;
    extern __shared__ char smem[];
    int tid = threadIdx.x;

    stage_b(smem, g_wC0h, g_wC0l, tid);
    stage_gather16(smem, tid >> 3, tid & 7, m0 + (tid >> 3), g_h, g_csrw0);
    __syncthreads();

    float acc[4][4] = {};
    mma_core(smem_u32(smem), acc);

    int lane = tid & 31, w = tid >> 5, wm = w & 1, wn = w >> 1;
    float s[2][2] = {}, s2[2][2] = {};
#pragma unroll
    for (int mt = 0; mt < 2; mt++)
#pragma unroll
        for (int half = 0; half < 2; half++) {
            int gr = m0 + wm * 32 + mt * 16 + (lane >> 2) + half * 8;
            if (gr >= N_NODES) continue;
            float* dst = g_x + (size_t)gr * HID;
            const float* hres = g_h + (size_t)gr * HID;
#pragma unroll
            for (int nt = 0; nt < 2; nt++) {
                int c = wn * 16 + nt * 8 + (lane & 3) * 2;
                float2 bb = *(const float2*)(b + c);
                float2 hv = *(const float2*)(hres + c);
                float2 o = {acc[mt * 2 + nt][half * 2 + 0] + bb.x + hv.x,
                            acc[mt * 2 + nt][half * 2 + 1] + bb.y + hv.y};
                *(float2*)(dst + c) = o;
                s[nt][0] += o.x;  s2[nt][0] += o.x * o.x;
                s[nt][1] += o.y;  s2[nt][1] += o.y * o.y;
            }
        }
#pragma unroll
    for (int d = 4; d < 32; d <<= 1)
#pragma unroll
        for (int nt = 0; nt < 2; nt++) {
            s[nt][0]  += __shfl_xor_sync(0xffffffffu, s[nt][0],  d);
            s[nt][1]  += __shfl_xor_sync(0xffffffffu, s[nt][1],  d);
            s2[nt][0] += __shfl_xor_sync(0xffffffffu, s2[nt][0], d);
            s2[nt][1] += __shfl_xor_sync(0xffffffffu, s2[nt][1], d);
        }
    if ((lane >> 2) == 0) {
#pragma unroll
        for (int nt = 0; nt < 2; nt++) {
            int c = wn * 16 + nt * 8 + (lane & 3) * 2;
            atomicAdd(&g_sum[c],       s[nt][0]);
            atomicAdd(&g_sum[c + 1],   s[nt][1]);
            atomicAdd(&g_sumsq[c],     s2[nt][0]);
            atomicAdd(&g_sumsq[c + 1], s2[nt][1]);
        }
    }
}

// out = gather(prelu(bn(x))) @ conv1_w + b, then log-softmax — all one kernel.
// BN scale/shift computed per-CTA into smem (B region, free during gather).
__global__ __launch_bounds__(512, 2) void k_mma_gemm1(
    const float* __restrict__ gamma, const float* __restrict__ beta,
    const float* __restrict__ prelu_a, const float* __restrict__ b,
    float* __restrict__ out) {
    const int m0 = blockIdx.x * MTILE;
    extern __shared__ char smem[];
    int tid = threadIdx.x;

    float* ssc = (float*)(smem + OFF_B_HI);
    float* ssh = ssc + HID;
    if (tid < HID) {
        int j = tid;
        float mean = g_sum[j] / (float)N_NODES;
        float var = g_sumsq[j] / (float)N_NODES - mean * mean;
        float sc = gamma[j] * rsqrtf(var + BN_EPS);
        ssc[j] = sc;
        ssh[j] = beta[j] - mean * sc;
    }
    __syncthreads();

    stage_gather_bn16(smem, tid >> 3, tid & 7, m0 + (tid >> 3), ssc, ssh,
                      __ldg(prelu_a));
    __syncthreads();  // gather done before B staging overwrites ssc/ssh

    int lane = tid & 31, w = tid >> 5, wm = w & 1, wn = w >> 1;

    for (int ny = 0; ny < 3; ny++) {
        if (ny) __syncthreads();  // prior mma reads of B done
        stage_b(smem, g_wC1h + (size_t)ny * 16384, g_wC1l + (size_t)ny * 16384, tid);
        __syncthreads();

        float acc[4][4] = {};
        mma_core(smem_u32(smem), acc);

        int n0 = ny * 128;
#pragma unroll
        for (int mt = 0; mt < 2; mt++)
#pragma unroll
            for (int half = 0; half < 2; half++) {
                int gr = m0 + wm * 32 + mt * 16 + (lane >> 2) + half * 8;
                if (gr >= N_NODES) continue;
                float* dst = out + (size_t)gr * OUTD;
#pragma unroll
                for (int nt = 0; nt < 2; nt++) {
                    int c = n0 + wn * 16 + nt * 8 + (lane & 3) * 2;
                    if (c < OUTD)
                        dst[c] = acc[mt * 2 + nt][half * 2 + 0] + b[c];
                    if (c + 1 < OUTD)
                        dst[c + 1] = acc[mt * 2 + nt][half * 2 + 1] + b[c + 1];
                }
            }
    }

    // ---- fused log-softmax over this CTA's 64 rows ----
    __syncthreads();
#pragma unroll
    for (int r4 = 0; r4 < 4; r4++) {
        int gr = m0 + w * 4 + r4;
        if (gr >= N_NODES) continue;
        float* row = out + (size_t)gr * OUTD;
        float v[11];
        float mx = -1e30f;
#pragma unroll
        for (int i = 0; i < 11; i++) {
            int c = lane + i * 32;
            v[i] = (c < OUTD) ? row[c] : -1e30f;
            mx = fmaxf(mx, v[i]);
        }
#pragma unroll
        for (int d = 16; d > 0; d >>= 1)
            mx = fmaxf(mx, __shfl_xor_sync(0xffffffffu, mx, d));
        float se = 0.f;
#pragma unroll
        for (int i = 0; i < 11; i++) se += __expf(v[i] - mx);
#pragma unroll
        for (int d = 16; d > 0; d >>= 1)
            se += __shfl_xor_sync(0xffffffffu, se, d);
        float lse = __logf(se) + mx;
#pragma unroll
        for (int i = 0; i < 11; i++) {
            int c = lane + i * 32;
            if (c < OUTD) row[c] = v[i] - lse;
        }
    }
}

// ---------------- launch ---------------------------------------------------
extern "C" void kernel_launch(void* const* d_in, const int* in_sizes, int n_in,
                              void* d_out, int out_size) {
    const float* x0 = (const float*)d_in[0];
    const float* x1 = (const float*)d_in[1];
    const int* edge_index = (const int*)d_in[2];
    const int* edge_type = (const int*)d_in[3];
    const int* node_type = (const int*)d_in[4];
    const int* lidx = (const int*)d_in[5];
    const float* lin0_w = (const float*)d_in[6];
    const float* lin0_b = (const float*)d_in[7];
    const float* lin1_w = (const float*)d_in[8];
    const float* lin1_b = (const float*)d_in[9];
    const float* conv0_w = (const float*)d_in[10];
    const float* conv0_b = (const float*)d_in[11];
    const float* conv0_rw = (const float*)d_in[12];
    const float* conv1_w = (const float*)d_in[13];
    const float* conv1_b = (const float*)d_in[14];
    const float* conv1_rw = (const float*)d_in[15];
    const float* bn_g = (const float*)d_in[16];
    const float* bn_b = (const float*)d_in[17];
    const float* prelu_a = (const float*)d_in[18];
    float* out = (float*)d_out;

    cudaFuncSetAttribute(k_mma_input, cudaFuncAttributeMaxDynamicSharedMemorySize, SMEM_MMA);
    cudaFuncSetAttribute(k_mma_gemm0, cudaFuncAttributeMaxDynamicSharedMemorySize, SMEM_MMA);
    cudaFuncSetAttribute(k_mma_gemm1, cudaFuncAttributeMaxDynamicSharedMemorySize, SMEM_MMA);

    k_init<<<(N_NODES + 255) / 256, 256>>>(conv0_rw, conv1_rw,
                                           lin0_w, lin1_w, conv0_w, conv1_w);
    k_part_deg<<<(N_EDGES + 255) / 256, 256>>>(node_type, edge_index, edge_type);
    k_scan1<<<NSCAN1, 1024>>>();
    k_scan23<<<(N_NODES + 255) / 256, 256>>>();
    k_fill<<<(N_EDGES + 255) / 256, 256>>>(edge_index, edge_type);

    // both input linears in one launch (+2 slack blocks for tile split)
    k_mma_input<<<NTILES_M + 2, 512, SMEM_MMA>>>(x0, x1, lidx, lin0_b, lin1_b);

    // layer 0: gather fused into GEMM staging; BN stats fused in epilogue
    k_mma_gemm0<<<NTILES_M, 512, SMEM_MMA>>>(conv0_b);

    // layer 1: BN finalize (per-CTA) + BN/PReLU-fused gather + GEMM + softmax
    k_mma_gemm1<<<NTILES_M, 512, SMEM_MMA>>>(bn_g, bn_b, prelu_a, conv1_b, out);
}

// round 15
// speedup vs baseline: 1.5815x; 1.5815x over previous
#include <cuda_runtime.h>
#include <cuda_fp16.h>
#include <cstdint>

#define N_NODES 100000
#define N_EDGES 500000
#define HID 128
#define OUTD 349
#define NET 8
#define BN_EPS 1e-5f
#define MTILE 64
#define NTILES_M ((N_NODES + MTILE - 1) / MTILE)  // 1563
#define NSCAN1 ((N_NODES + 1023) / 1024)          // 98

// ---------------- scratch (static device globals; no allocation) ----------
__device__ float g_h[N_NODES * HID];     // input-linear output; later y = prelu(bn(x))
__device__ float g_x[N_NODES * HID];     // conv0 out + residual (BN input)
__device__ float g_deg0[N_NODES], g_deg1[N_NODES];
__device__ int   g_count[N_NODES];
__device__ int   g_csroff[N_NODES + 1];
__device__ int   g_cursor[N_NODES];
__device__ int   g_bsum[NSCAN1];
__device__ int   g_csrsrc[N_EDGES];
__device__ float g_csrw0[N_EDGES], g_csrw1[N_EDGES];
__device__ float g_rws[2 * NET];
__device__ float g_sum[HID], g_sumsq[HID];
__device__ int   g_cnt[2];
__device__ int   g_list0[N_NODES], g_list1[N_NODES];

// fp16 hi/lo weight images, layout [tile][k=128][n=128] row-major
__device__ __half g_wI0h[16384], g_wI0l[16384];       // lin0_w
__device__ __half g_wI1h[16384], g_wI1l[16384];       // lin1_w
__device__ __half g_wC0h[16384], g_wC0l[16384];       // conv0_w
__device__ __half g_wC1h[3 * 16384], g_wC1l[3 * 16384];  // conv1_w (3 tiles)

// ---------------- mma.sync GEMM machinery ----------------------------------
// A in fp16 (truncated), W split hi+lo fp16 -> 2 mma terms. 512 threads/CTA.
#define ROWB 272                    // 136 fp16 padded row (conflict-free LDSM)
#define OFF_A    0                  // 64 x 272 = 17408
#define OFF_B_HI 17408              // 128 x 272 = 34816
#define OFF_B_LO 52224
#define SMEM_MMA 87040              // 85KB -> 2 CTAs/SM

__device__ __forceinline__ uint32_t smem_u32(const void* p) {
    uint32_t a;
    asm("{ .reg .u64 t; cvta.to.shared.u64 t, %1; cvt.u32.u64 %0, t; }"
        : "=r"(a) : "l"(p));
    return a;
}

__device__ __forceinline__ void ldsm4(uint32_t addr, uint32_t* r) {
    asm volatile("ldmatrix.sync.aligned.m8n8.x4.shared.b16 {%0,%1,%2,%3}, [%4];"
                 : "=r"(r[0]), "=r"(r[1]), "=r"(r[2]), "=r"(r[3]) : "r"(addr));
}
__device__ __forceinline__ void ldsm2t(uint32_t addr, uint32_t* r) {
    asm volatile("ldmatrix.sync.aligned.m8n8.x2.trans.shared.b16 {%0,%1}, [%2];"
                 : "=r"(r[0]), "=r"(r[1]) : "r"(addr));
}
__device__ __forceinline__ void mma16816(float* d, const uint32_t* a, const uint32_t* b) {
    asm volatile(
        "mma.sync.aligned.m16n8k16.row.col.f32.f16.f16.f32 "
        "{%0,%1,%2,%3}, {%4,%5,%6,%7}, {%8,%9}, {%0,%1,%2,%3};"
        : "+f"(d[0]), "+f"(d[1]), "+f"(d[2]), "+f"(d[3])
        : "r"(a[0]), "r"(a[1]), "r"(a[2]), "r"(a[3]), "r"(b[0]), "r"(b[1]));
}

// write 16 fp32 (one eighth-row) as packed fp16 into the A tile
__device__ __forceinline__ void stage_write16(char* smem, int row, int oct,
                                              const float* a) {
    uint32_t off = (uint32_t)row * ROWB + oct * 32;
#pragma unroll
    for (int g = 0; g < 2; g++) {
        uint32_t p[4];
#pragma unroll
        for (int i = 0; i < 4; i++)
            asm("cvt.rn.f16x2.f32 %0, %1, %2;"
                : "=r"(p[i]) : "f"(a[g * 8 + 2 * i + 1]), "f"(a[g * 8 + 2 * i]));
        *reinterpret_cast<uint4*>(smem + OFF_A + off + g * 16) =
            make_uint4(p[0], p[1], p[2], p[3]);
    }
}

// stage 16 fp32 (eighth row) from a contiguous source row
__device__ __forceinline__ void stage_plain16(char* smem, int row, int oct,
                                              const float* src) {
    float f[16];
    if (src) {
#pragma unroll
        for (int g = 0; g < 4; g++) {
            float4 v = ((const float4*)src)[g];
            f[g * 4 + 0] = v.x; f[g * 4 + 1] = v.y;
            f[g * 4 + 2] = v.z; f[g * 4 + 3] = v.w;
        }
    } else {
#pragma unroll
        for (int i = 0; i < 16; i++) f[i] = 0.f;
    }
    stage_write16(smem, row, oct, f);
}

// gather-aggregate an eighth row over incoming edges
__device__ __forceinline__ void stage_gather16(char* smem, int row, int oct, int gr,
                                               const float* srcbase,
                                               const float* warr) {
    float a[16];
#pragma unroll
    for (int i = 0; i < 16; i++) a[i] = 0.f;
    if (gr < N_NODES) {
        int s0 = g_csroff[gr], s1 = g_csroff[gr + 1];
#pragma unroll 2
        for (int e = s0; e < s1; e++) {
            int src = g_csrsrc[e];
            float w = warr[e];
            const float4* p = (const float4*)(srcbase + (size_t)src * HID + oct * 16);
#pragma unroll
            for (int g = 0; g < 4; g++) {
                float4 v = __ldg(&p[g]);
                a[g * 4 + 0] += w * v.x; a[g * 4 + 1] += w * v.y;
                a[g * 4 + 2] += w * v.z; a[g * 4 + 3] += w * v.w;
            }
        }
    }
    stage_write16(smem, row, oct, a);
}

// copy one pre-split B tile (hi/lo [k][n] images) into padded smem rows
__device__ __forceinline__ void stage_b(char* smem, const __half* bh,
                                        const __half* bl, int tid) {
    const uint4* h4 = (const uint4*)bh;
    const uint4* l4 = (const uint4*)bl;
    for (int i = tid; i < 2048; i += 512) {
        int k = i >> 4, s = i & 15;
        *(uint4*)(smem + OFF_B_HI + k * ROWB + s * 16) = h4[i];
        *(uint4*)(smem + OFF_B_LO + k * ROWB + s * 16) = l4[i];
    }
}

// core: 16 warps; warp (wm=w&1, wn=w>>1 in 0..7): rows wm*32..+31, cols wn*16..+15
__device__ __forceinline__ void mma_core(uint32_t sb, float acc[4][4]) {
    int lane = threadIdx.x & 31;
    int w = threadIdx.x >> 5;
    int wm = w & 1, wn = w >> 1;
    uint32_t aaddr[2], baddr[2];
#pragma unroll
    for (int mt = 0; mt < 2; mt++)
        aaddr[mt] = sb + OFF_A +
                    (uint32_t)(wm * 32 + mt * 16 + (lane & 15)) * ROWB +
                    (lane >> 4) * 16;
#pragma unroll
    for (int nt = 0; nt < 2; nt++)
        baddr[nt] = sb + OFF_B_HI + (uint32_t)(lane & 15) * ROWB +
                    (wn * 16 + nt * 8) * 2;
#pragma unroll
    for (int ks = 0; ks < 8; ks++) {
        uint32_t bh[2][2], bl[2][2];
#pragma unroll
        for (int nt = 0; nt < 2; nt++) {
            uint32_t ba = baddr[nt] + ks * (16 * ROWB);
            ldsm2t(ba, bh[nt]);
            ldsm2t(ba + (OFF_B_LO - OFF_B_HI), bl[nt]);
        }
#pragma unroll
        for (int mt = 0; mt < 2; mt++) {
            uint32_t ah[4];
            ldsm4(aaddr[mt] + ks * 32, ah);
#pragma unroll
            for (int nt = 0; nt < 2; nt++) {
                mma16816(acc[mt * 2 + nt], ah, bh[nt]);
                mma16816(acc[mt * 2 + nt], ah, bl[nt]);
            }
        }
    }
}

// ---------------- prep ----------------------------------------------------
// zero/init + relation weights + ALL weight hi/lo images in one launch
__global__ void k_init(const float* __restrict__ rw0, const float* __restrict__ rw1,
                       const float* __restrict__ lin0_w,
                       const float* __restrict__ lin1_w,
                       const float* __restrict__ conv0_w,
                       const float* __restrict__ conv1_w) {
    int i = blockIdx.x * blockDim.x + threadIdx.x;
    if (i < N_NODES) { g_deg0[i] = 0.0f; g_deg1[i] = 0.0f; g_count[i] = 0; }
    if (i < HID)     { g_sum[i] = 0.0f;  g_sumsq[i] = 0.0f; }
    if (i < 2)       { g_cnt[i] = 0; }
    if (i < NET) {
        float v = rw0[i] * 100.0f;
        g_rws[i] = (v >= 0.0f) ? v : 0.01f * v;
    } else if (i < 2 * NET) {
        float v = rw1[i - NET] * 100.0f;
        g_rws[i] = (v >= 0.0f) ? v : 0.01f * v;
    }
    if (i < 6 * 16384) {
        int img = i >> 14;
        int rem = i & 16383;
        int k = rem >> 7, n = rem & 127;
        const float* W;
        int ncols, col, off;
        __half *hi, *lo;
        if (img == 0)      { W = lin0_w;  ncols = HID;  col = n; hi = g_wI0h; lo = g_wI0l; off = rem; }
        else if (img == 1) { W = lin1_w;  ncols = HID;  col = n; hi = g_wI1h; lo = g_wI1l; off = rem; }
        else if (img == 2) { W = conv0_w; ncols = HID;  col = n; hi = g_wC0h; lo = g_wC0l; off = rem; }
        else { int t = img - 3; W = conv1_w; ncols = OUTD; col = t * 128 + n;
               hi = g_wC1h; lo = g_wC1l; off = t * 16384 + rem; }
        float v = (col < ncols) ? W[(size_t)k * ncols + col] : 0.f;
        __half h = __float2half_rn(v);
        hi[off] = h;
        lo[off] = __float2half_rn(v - __half2float(h));
    }
}

// partition (warp-aggregated) + degree/count accumulation in one launch
__global__ void k_part_deg(const int* __restrict__ ntype,
                           const int* __restrict__ ei,
                           const int* __restrict__ et) {
    int i = blockIdx.x * blockDim.x + threadIdx.x;
    int lane = threadIdx.x & 31;
    int t = (i < N_NODES) ? ntype[i] : -1;
#pragma unroll
    for (int tt = 0; tt < 2; tt++) {
        unsigned m = __ballot_sync(0xffffffffu, t == tt);
        if (t == tt) {
            int leader = __ffs(m) - 1;
            int pos = 0;
            if (lane == leader) pos = atomicAdd(&g_cnt[tt], __popc(m));
            pos = __shfl_sync(m, pos, leader);
            pos += __popc(m & ((1u << lane) - 1u));
            if (tt == 0) g_list0[pos] = i; else g_list1[pos] = i;
        }
    }
    if (i < N_EDGES) {
        int c = ei[N_EDGES + i];
        int ty = et[i];
        atomicAdd(&g_deg0[c], g_rws[ty]);
        atomicAdd(&g_deg1[c], g_rws[NET + ty]);
        atomicAdd(&g_count[c], 1);
    }
}

// phase 1 of scan: per-1024-block exclusive scan + block sums
__global__ __launch_bounds__(1024) void k_scan1() {
    __shared__ int s[1024];
    int tid = threadIdx.x;
    int i = blockIdx.x * 1024 + tid;
    int v = (i < N_NODES) ? g_count[i] : 0;
    s[tid] = v;
    __syncthreads();
#pragma unroll
    for (int d = 1; d < 1024; d <<= 1) {
        int t = (tid >= d) ? s[tid - d] : 0;
        __syncthreads();
        s[tid] += t;
        __syncthreads();
    }
    if (i < N_NODES) g_csroff[i] = s[tid] - v;
    if (tid == 1023) g_bsum[blockIdx.x] = s[1023];
}

// phase 2+3 merged: each block redundantly scans the 98 block sums, then
// applies the prefix to its 256 csroff entries.
__global__ __launch_bounds__(256) void k_scan23() {
    __shared__ int wsum[4];
    __shared__ int ex[128];
    int tid = threadIdx.x, lane = tid & 31, wid = tid >> 5;
    int v = 0, x = 0;
    if (tid < 128) {
        v = (tid < NSCAN1) ? g_bsum[tid] : 0;
        x = v;
#pragma unroll
        for (int d = 1; d < 32; d <<= 1) {
            int t = __shfl_up_sync(0xffffffffu, x, d);
            if (lane >= d) x += t;
        }
        if (lane == 31) wsum[wid] = x;
    }
    __syncthreads();
    if (tid < 128) {
        int base = 0;
#pragma unroll
        for (int k = 0; k < 4; k++) base += (k < wid) ? wsum[k] : 0;
        ex[tid] = base + x - v;  // exclusive prefix of block sums
    }
    __syncthreads();
    int i = blockIdx.x * blockDim.x + tid;
    if (i < N_NODES) {
        int o = g_csroff[i] + ex[i >> 10];
        g_csroff[i] = o;
        g_cursor[i] = o;
    }
    if (i == 0) g_csroff[N_NODES] = N_EDGES;
}

__global__ void k_fill(const int* __restrict__ ei, const int* __restrict__ et) {
    int e = blockIdx.x * blockDim.x + threadIdx.x;
    if (e >= N_EDGES) return;
    int r = ei[e];
    int c = ei[N_EDGES + e];
    int t = et[e];
    int pos = atomicAdd(&g_cursor[c], 1);
    g_csrsrc[pos] = r;
    g_csrw0[pos] = g_rws[t] / fabsf(g_deg0[c]);
    g_csrw1[pos] = g_rws[NET + t] / fabsf(g_deg1[c]);
}

// ---------------- mma GEMM kernels (512 threads) ---------------------------

// both input linears in ONE launch: blocks [0, nt0) do type 0, rest type 1
__global__ __launch_bounds__(512, 2) void k_mma_input(
    const float* __restrict__ x0, const float* __restrict__ x1,
    const int* __restrict__ lidx,
    const float* __restrict__ b0, const float* __restrict__ b1) {
    const int cnt0 = g_cnt[0], cnt1 = g_cnt[1];
    const int nt0 = (cnt0 + MTILE - 1) / MTILE;
    int pass, tile;
    if ((int)blockIdx.x < nt0) { pass = 0; tile = blockIdx.x; }
    else { pass = 1; tile = blockIdx.x - nt0; }
    const int cnt = pass ? cnt1 : cnt0;
    const int m0 = tile * MTILE;
    if (m0 >= cnt) return;
    const int* list = pass ? g_list1 : g_list0;
    const float* xk = pass ? x1 : x0;
    const float* b = pass ? b1 : b0;
    extern __shared__ char smem[];
    int tid = threadIdx.x;

    stage_b(smem, pass ? g_wI1h : g_wI0h, pass ? g_wI1l : g_wI0l, tid);
    {
        int row = tid >> 3, oct = tid & 7;
        int lr = m0 + row;
        const float* src = nullptr;
        if (lr < cnt) src = xk + (size_t)lidx[list[lr]] * HID + oct * 16;
        stage_plain16(smem, row, oct, src);
    }
    __syncthreads();

    float acc[4][4] = {};
    mma_core(smem_u32(smem), acc);

    int lane = tid & 31, w = tid >> 5, wm = w & 1, wn = w >> 1;
#pragma unroll
    for (int mt = 0; mt < 2; mt++)
#pragma unroll
        for (int half = 0; half < 2; half++) {
            int lr = m0 + wm * 32 + mt * 16 + (lane >> 2) + half * 8;
            if (lr >= cnt) continue;
            float* dst = g_h + (size_t)list[lr] * HID;
#pragma unroll
            for (int nt = 0; nt < 2; nt++) {
                int c = wn * 16 + nt * 8 + (lane & 3) * 2;
                float2 bb = *(const float2*)(b + c);
                float2 o = {acc[mt * 2 + nt][half * 2 + 0] + bb.x,
                            acc[mt * 2 + nt][half * 2 + 1] + bb.y};
                *(float2*)(dst + c) = o;
            }
        }
}

// g_x = gather(h) @ conv0_w + b + g_h ; BN stats fused in epilogue
__global__ __launch_bounds__(512, 2) void k_mma_gemm0(const float* __restrict__ b) {
    const int m0 = blockIdx.x * MTILE;
    extern __shared__ char smem[];
    int tid = threadIdx.x;

    stage_b(smem, g_wC0h, g_wC0l, tid);
    stage_gather16(smem, tid >> 3, tid & 7, m0 + (tid >> 3), g_h, g_csrw0);
    __syncthreads();

    float acc[4][4] = {};
    mma_core(smem_u32(smem), acc);

    int lane = tid & 31, w = tid >> 5, wm = w & 1, wn = w >> 1;
    float s[2][2] = {}, s2[2][2] = {};
#pragma unroll
    for (int mt = 0; mt < 2; mt++)
#pragma unroll
        for (int half = 0; half < 2; half++) {
            int gr = m0 + wm * 32 + mt * 16 + (lane >> 2) + half * 8;
            if (gr >= N_NODES) continue;
            float* dst = g_x + (size_t)gr * HID;
            const float* hres = g_h + (size_t)gr * HID;
#pragma unroll
            for (int nt = 0; nt < 2; nt++) {
                int c = wn * 16 + nt * 8 + (lane & 3) * 2;
                float2 bb = *(const float2*)(b + c);
                float2 hv = *(const float2*)(hres + c);
                float2 o = {acc[mt * 2 + nt][half * 2 + 0] + bb.x + hv.x,
                            acc[mt * 2 + nt][half * 2 + 1] + bb.y + hv.y};
                *(float2*)(dst + c) = o;
                s[nt][0] += o.x;  s2[nt][0] += o.x * o.x;
                s[nt][1] += o.y;  s2[nt][1] += o.y * o.y;
            }
        }
#pragma unroll
    for (int d = 4; d < 32; d <<= 1)
#pragma unroll
        for (int nt = 0; nt < 2; nt++) {
            s[nt][0]  += __shfl_xor_sync(0xffffffffu, s[nt][0],  d);
            s[nt][1]  += __shfl_xor_sync(0xffffffffu, s[nt][1],  d);
            s2[nt][0] += __shfl_xor_sync(0xffffffffu, s2[nt][0], d);
            s2[nt][1] += __shfl_xor_sync(0xffffffffu, s2[nt][1], d);
        }
    if ((lane >> 2) == 0) {
#pragma unroll
        for (int nt = 0; nt < 2; nt++) {
            int c = wn * 16 + nt * 8 + (lane & 3) * 2;
            atomicAdd(&g_sum[c],       s[nt][0]);
            atomicAdd(&g_sum[c + 1],   s[nt][1]);
            atomicAdd(&g_sumsq[c],     s2[nt][0]);
            atomicAdd(&g_sumsq[c + 1], s2[nt][1]);
        }
    }
}

// out = gather(y) @ conv1_w + b, then log-softmax in the same kernel
__global__ __launch_bounds__(512, 2) void k_mma_gemm1(const float* __restrict__ b,
                                                      float* __restrict__ out) {
    const int m0 = blockIdx.x * MTILE;
    extern __shared__ char smem[];
    int tid = threadIdx.x;

    stage_gather16(smem, tid >> 3, tid & 7, m0 + (tid >> 3), g_h, g_csrw1);

    int lane = tid & 31, w = tid >> 5, wm = w & 1, wn = w >> 1;

    for (int ny = 0; ny < 3; ny++) {
        if (ny) __syncthreads();  // prior mma reads of B done
        stage_b(smem, g_wC1h + (size_t)ny * 16384, g_wC1l + (size_t)ny * 16384, tid);
        __syncthreads();

        float acc[4][4] = {};
        mma_core(smem_u32(smem), acc);

        int n0 = ny * 128;
#pragma unroll
        for (int mt = 0; mt < 2; mt++)
#pragma unroll
            for (int half = 0; half < 2; half++) {
                int gr = m0 + wm * 32 + mt * 16 + (lane >> 2) + half * 8;
                if (gr >= N_NODES) continue;
                float* dst = out + (size_t)gr * OUTD;
#pragma unroll
                for (int nt = 0; nt < 2; nt++) {
                    int c = n0 + wn * 16 + nt * 8 + (lane & 3) * 2;
                    if (c < OUTD)
                        dst[c] = acc[mt * 2 + nt][half * 2 + 0] + b[c];
                    if (c + 1 < OUTD)
                        dst[c + 1] = acc[mt * 2 + nt][half * 2 + 1] + b[c + 1];
                }
            }
    }

    // ---- fused log-softmax over this CTA's 64 rows ----
    __syncthreads();
#pragma unroll
    for (int r4 = 0; r4 < 4; r4++) {
        int gr = m0 + w * 4 + r4;
        if (gr >= N_NODES) continue;
        float* row = out + (size_t)gr * OUTD;
        float v[11];
        float mx = -1e30f;
#pragma unroll
        for (int i = 0; i < 11; i++) {
            int c = lane + i * 32;
            v[i] = (c < OUTD) ? row[c] : -1e30f;
            mx = fmaxf(mx, v[i]);
        }
#pragma unroll
        for (int d = 16; d > 0; d >>= 1)
            mx = fmaxf(mx, __shfl_xor_sync(0xffffffffu, mx, d));
        float se = 0.f;
#pragma unroll
        for (int i = 0; i < 11; i++) se += __expf(v[i] - mx);
#pragma unroll
        for (int d = 16; d > 0; d >>= 1)
            se += __shfl_xor_sync(0xffffffffu, se, d);
        float lse = __logf(se) + mx;
#pragma unroll
        for (int i = 0; i < 11; i++) {
            int c = lane + i * 32;
            if (c < OUTD) row[c] = v[i] - lse;
        }
    }
}

// ---------------- BN (finalize + apply in one kernel) ----------------------
__global__ void k_bnapply(const float* __restrict__ gamma,
                          const float* __restrict__ beta,
                          const float* __restrict__ prelu_a) {
    __shared__ float ssc[HID], ssh[HID];
    if (threadIdx.x < HID) {
        int j = threadIdx.x;
        float mean = g_sum[j] / (float)N_NODES;
        float var = g_sumsq[j] / (float)N_NODES - mean * mean;
        float sc = gamma[j] * rsqrtf(var + BN_EPS);
        ssc[j] = sc;
        ssh[j] = beta[j] - mean * sc;
    }
    __syncthreads();
    const float a = __ldg(prelu_a);
    const int total = N_NODES * HID / 4;
    for (int i = blockIdx.x * blockDim.x + threadIdx.x; i < total;
         i += gridDim.x * blockDim.x) {
        int kk = i & 31;
        float4 x = ((const float4*)g_x)[i];
        float4 sc = ((const float4*)ssc)[kk];
        float4 sh = ((const float4*)ssh)[kk];
        float4 v;
        v.x = x.x * sc.x + sh.x;
        v.y = x.y * sc.y + sh.y;
        v.z = x.z * sc.z + sh.z;
        v.w = x.w * sc.w + sh.w;
        v.x = (v.x >= 0.f) ? v.x : a * v.x;
        v.y = (v.y >= 0.f) ? v.y : a * v.y;
        v.z = (v.z >= 0.f) ? v.z : a * v.z;
        v.w = (v.w >= 0.f) ? v.w : a * v.w;
        ((float4*)g_h)[i] = v;
    }
}

// ---------------- launch ---------------------------------------------------
extern "C" void kernel_launch(void* const* d_in, const int* in_sizes, int n_in,
                              void* d_out, int out_size) {
    const float* x0 = (const float*)d_in[0];
    const float* x1 = (const float*)d_in[1];
    const int* edge_index = (const int*)d_in[2];
    const int* edge_type = (const int*)d_in[3];
    const int* node_type = (const int*)d_in[4];
    const int* lidx = (const int*)d_in[5];
    const float* lin0_w = (const float*)d_in[6];
    const float* lin0_b = (const float*)d_in[7];
    const float* lin1_w = (const float*)d_in[8];
    const float* lin1_b = (const float*)d_in[9];
    const float* conv0_w = (const float*)d_in[10];
    const float* conv0_b = (const float*)d_in[11];
    const float* conv0_rw = (const float*)d_in[12];
    const float* conv1_w = (const float*)d_in[13];
    const float* conv1_b = (const float*)d_in[14];
    const float* conv1_rw = (const float*)d_in[15];
    const float* bn_g = (const float*)d_in[16];
    const float* bn_b = (const float*)d_in[17];
    const float* prelu_a = (const float*)d_in[18];
    float* out = (float*)d_out;

    cudaFuncSetAttribute(k_mma_input, cudaFuncAttributeMaxDynamicSharedMemorySize, SMEM_MMA);
    cudaFuncSetAttribute(k_mma_gemm0, cudaFuncAttributeMaxDynamicSharedMemorySize, SMEM_MMA);
    cudaFuncSetAttribute(k_mma_gemm1, cudaFuncAttributeMaxDynamicSharedMemorySize, SMEM_MMA);

    k_init<<<(N_NODES + 255) / 256, 256>>>(conv0_rw, conv1_rw,
                                           lin0_w, lin1_w, conv0_w, conv1_w);
    k_part_deg<<<(N_EDGES + 255) / 256, 256>>>(node_type, edge_index, edge_type);
    k_scan1<<<NSCAN1, 1024>>>();
    k_scan23<<<(N_NODES + 255) / 256, 256>>>();
    k_fill<<<(N_EDGES + 255) / 256, 256>>>(edge_index, edge_type);

    // both input linears in one launch (+2 slack blocks for tile split)
    k_mma_input<<<NTILES_M + 2, 512, SMEM_MMA>>>(x0, x1, lidx, lin0_b, lin1_b);

    // layer 0: gather fused into GEMM staging; BN stats fused in epilogue
    k_mma_gemm0<<<NTILES_M, 512, SMEM_MMA>>>(conv0_b);
    k_bnapply<<<2048, 256>>>(bn_g, bn_b, prelu_a);

    // layer 1: gather of y fused into GEMM staging + softmax
    k_mma_gemm1<<<NTILES_M, 512, SMEM_MMA>>>(conv1_b, out);
}

// round 16
// speedup vs baseline: 1.7870x; 1.1299x over previous
#include <cuda_runtime.h>
#include <cuda_fp16.h>
#include <cstdint>

#define N_NODES 100000
#define N_EDGES 500000
#define HID 128
#define OUTD 349
#define NET 8
#define BN_EPS 1e-5f
#define MTILE 64
#define NTILES_M ((N_NODES + MTILE - 1) / MTILE)  // 1563
#define NSCAN1 ((N_NODES + 1023) / 1024)          // 98

// ---------------- scratch (static device globals; no allocation) ----------
__device__ float g_h[N_NODES * HID];     // input-linear output; later y = prelu(bn(x))
__device__ float g_x[N_NODES * HID];     // conv0 out + residual (BN input)
__device__ float g_deg0[N_NODES], g_deg1[N_NODES];
__device__ int   g_count[N_NODES];
__device__ int   g_csroff[N_NODES + 1];
__device__ int   g_cursor[N_NODES];
__device__ int   g_bsum[NSCAN1];
__device__ int   g_csrsrc[N_EDGES];
__device__ float g_csrw0[N_EDGES], g_csrw1[N_EDGES];
__device__ float g_rws[2 * NET];
__device__ float g_sum[HID], g_sumsq[HID];
__device__ int   g_cnt[2];
__device__ int   g_list0[N_NODES], g_list1[N_NODES];

// fp16 weight images, layout [tile][k=128][n=128] row-major
__device__ __half g_wI0[16384];            // lin0_w
__device__ __half g_wI1[16384];            // lin1_w
__device__ __half g_wC0[16384];            // conv0_w
__device__ __half g_wC1[3 * 16384];        // conv1_w (3 tiles)

// ---------------- mma.sync GEMM machinery ----------------------------------
// A fp16, W fp16 (single term). 512 threads/CTA, 3 CTAs/SM.
#define ROWB 272                    // 136 fp16 padded row (conflict-free LDSM)
#define OFF_A   0                   // 64 x 272 = 17408
#define OFF_B   17408               // 128 x 272 = 34816
#define SMEM_MMA 52224              // 51KB -> 3 CTAs/SM (reg-capped)

__device__ __forceinline__ uint32_t smem_u32(const void* p) {
    uint32_t a;
    asm("{ .reg .u64 t; cvta.to.shared.u64 t, %1; cvt.u32.u64 %0, t; }"
        : "=r"(a) : "l"(p));
    return a;
}

__device__ __forceinline__ void ldsm4(uint32_t addr, uint32_t* r) {
    asm volatile("ldmatrix.sync.aligned.m8n8.x4.shared.b16 {%0,%1,%2,%3}, [%4];"
                 : "=r"(r[0]), "=r"(r[1]), "=r"(r[2]), "=r"(r[3]) : "r"(addr));
}
__device__ __forceinline__ void ldsm2t(uint32_t addr, uint32_t* r) {
    asm volatile("ldmatrix.sync.aligned.m8n8.x2.trans.shared.b16 {%0,%1}, [%2];"
                 : "=r"(r[0]), "=r"(r[1]) : "r"(addr));
}
__device__ __forceinline__ void mma16816(float* d, const uint32_t* a, const uint32_t* b) {
    asm volatile(
        "mma.sync.aligned.m16n8k16.row.col.f32.f16.f16.f32 "
        "{%0,%1,%2,%3}, {%4,%5,%6,%7}, {%8,%9}, {%0,%1,%2,%3};"
        : "+f"(d[0]), "+f"(d[1]), "+f"(d[2]), "+f"(d[3])
        : "r"(a[0]), "r"(a[1]), "r"(a[2]), "r"(a[3]), "r"(b[0]), "r"(b[1]));
}

// write 16 fp32 (one eighth-row) as packed fp16 into the A tile
__device__ __forceinline__ void stage_write16(char* smem, int row, int oct,
                                              const float* a) {
    uint32_t off = (uint32_t)row * ROWB + oct * 32;
#pragma unroll
    for (int g = 0; g < 2; g++) {
        uint32_t p[4];
#pragma unroll
        for (int i = 0; i < 4; i++)
            asm("cvt.rn.f16x2.f32 %0, %1, %2;"
                : "=r"(p[i]) : "f"(a[g * 8 + 2 * i + 1]), "f"(a[g * 8 + 2 * i]));
        *reinterpret_cast<uint4*>(smem + OFF_A + off + g * 16) =
            make_uint4(p[0], p[1], p[2], p[3]);
    }
}

// stage 16 fp32 (eighth row) from a contiguous source row
__device__ __forceinline__ void stage_plain16(char* smem, int row, int oct,
                                              const float* src) {
    float f[16];
    if (src) {
#pragma unroll
        for (int g = 0; g < 4; g++) {
            float4 v = ((const float4*)src)[g];
            f[g * 4 + 0] = v.x; f[g * 4 + 1] = v.y;
            f[g * 4 + 2] = v.z; f[g * 4 + 3] = v.w;
        }
    } else {
#pragma unroll
        for (int i = 0; i < 16; i++) f[i] = 0.f;
    }
    stage_write16(smem, row, oct, f);
}

// gather-aggregate an eighth row over incoming edges
__device__ __forceinline__ void stage_gather16(char* smem, int row, int oct, int gr,
                                               const float* srcbase,
                                               const float* warr) {
    float a[16];
#pragma unroll
    for (int i = 0; i < 16; i++) a[i] = 0.f;
    if (gr < N_NODES) {
        int s0 = g_csroff[gr], s1 = g_csroff[gr + 1];
#pragma unroll 2
        for (int e = s0; e < s1; e++) {
            int src = g_csrsrc[e];
            float w = warr[e];
            const float4* p = (const float4*)(srcbase + (size_t)src * HID + oct * 16);
#pragma unroll
            for (int g = 0; g < 4; g++) {
                float4 v = __ldg(&p[g]);
                a[g * 4 + 0] += w * v.x; a[g * 4 + 1] += w * v.y;
                a[g * 4 + 2] += w * v.z; a[g * 4 + 3] += w * v.w;
            }
        }
    }
    stage_write16(smem, row, oct, a);
}

// copy one fp16 B tile ([k][n] image) into padded smem rows
__device__ __forceinline__ void stage_b(char* smem, const __half* bt, int tid) {
    const uint4* h4 = (const uint4*)bt;
    for (int i = tid; i < 2048; i += 512) {
        int k = i >> 4, s = i & 15;
        *(uint4*)(smem + OFF_B + k * ROWB + s * 16) = h4[i];
    }
}

// core: 16 warps; warp (wm=w&1, wn=w>>1 in 0..7): rows wm*32..+31, cols wn*16..+15
__device__ __forceinline__ void mma_core(uint32_t sb, float acc[4][4]) {
    int lane = threadIdx.x & 31;
    int w = threadIdx.x >> 5;
    int wm = w & 1, wn = w >> 1;
    uint32_t aaddr[2], baddr[2];
#pragma unroll
    for (int mt = 0; mt < 2; mt++)
        aaddr[mt] = sb + OFF_A +
                    (uint32_t)(wm * 32 + mt * 16 + (lane & 15)) * ROWB +
                    (lane >> 4) * 16;
#pragma unroll
    for (int nt = 0; nt < 2; nt++)
        baddr[nt] = sb + OFF_B + (uint32_t)(lane & 15) * ROWB +
                    (wn * 16 + nt * 8) * 2;
#pragma unroll
    for (int ks = 0; ks < 8; ks++) {
        uint32_t bh[2][2];
#pragma unroll
        for (int nt = 0; nt < 2; nt++)
            ldsm2t(baddr[nt] + ks * (16 * ROWB), bh[nt]);
#pragma unroll
        for (int mt = 0; mt < 2; mt++) {
            uint32_t ah[4];
            ldsm4(aaddr[mt] + ks * 32, ah);
#pragma unroll
            for (int nt = 0; nt < 2; nt++)
                mma16816(acc[mt * 2 + nt], ah, bh[nt]);
        }
    }
}

// ---------------- prep ----------------------------------------------------
// zero/init + relation weights + ALL fp16 weight images in one launch
__global__ void k_init(const float* __restrict__ rw0, const float* __restrict__ rw1,
                       const float* __restrict__ lin0_w,
                       const float* __restrict__ lin1_w,
                       const float* __restrict__ conv0_w,
                       const float* __restrict__ conv1_w) {
    int i = blockIdx.x * blockDim.x + threadIdx.x;
    if (i < N_NODES) { g_deg0[i] = 0.0f; g_deg1[i] = 0.0f; g_count[i] = 0; }
    if (i < HID)     { g_sum[i] = 0.0f;  g_sumsq[i] = 0.0f; }
    if (i < 2)       { g_cnt[i] = 0; }
    if (i < NET) {
        float v = rw0[i] * 100.0f;
        g_rws[i] = (v >= 0.0f) ? v : 0.01f * v;
    } else if (i < 2 * NET) {
        float v = rw1[i - NET] * 100.0f;
        g_rws[i] = (v >= 0.0f) ? v : 0.01f * v;
    }
    if (i < 6 * 16384) {
        int img = i >> 14;
        int rem = i & 16383;
        int k = rem >> 7, n = rem & 127;
        const float* W;
        int ncols, col, off;
        __half* hi;
        if (img == 0)      { W = lin0_w;  ncols = HID;  col = n; hi = g_wI0; off = rem; }
        else if (img == 1) { W = lin1_w;  ncols = HID;  col = n; hi = g_wI1; off = rem; }
        else if (img == 2) { W = conv0_w; ncols = HID;  col = n; hi = g_wC0; off = rem; }
        else { int t = img - 3; W = conv1_w; ncols = OUTD; col = t * 128 + n;
               hi = g_wC1; off = t * 16384 + rem; }
        float v = (col < ncols) ? W[(size_t)k * ncols + col] : 0.f;
        hi[off] = __float2half_rn(v);
    }
}

// partition (warp-aggregated) + degree/count accumulation in one launch
__global__ void k_part_deg(const int* __restrict__ ntype,
                           const int* __restrict__ ei,
                           const int* __restrict__ et) {
    int i = blockIdx.x * blockDim.x + threadIdx.x;
    int lane = threadIdx.x & 31;
    int t = (i < N_NODES) ? ntype[i] : -1;
#pragma unroll
    for (int tt = 0; tt < 2; tt++) {
        unsigned m = __ballot_sync(0xffffffffu, t == tt);
        if (t == tt) {
            int leader = __ffs(m) - 1;
            int pos = 0;
            if (lane == leader) pos = atomicAdd(&g_cnt[tt], __popc(m));
            pos = __shfl_sync(m, pos, leader);
            pos += __popc(m & ((1u << lane) - 1u));
            if (tt == 0) g_list0[pos] = i; else g_list1[pos] = i;
        }
    }
    if (i < N_EDGES) {
        int c = ei[N_EDGES + i];
        int ty = et[i];
        atomicAdd(&g_deg0[c], g_rws[ty]);
        atomicAdd(&g_deg1[c], g_rws[NET + ty]);
        atomicAdd(&g_count[c], 1);
    }
}

// phase 1 of scan: per-1024-block exclusive scan + block sums
__global__ __launch_bounds__(1024) void k_scan1() {
    __shared__ int s[1024];
    int tid = threadIdx.x;
    int i = blockIdx.x * 1024 + tid;
    int v = (i < N_NODES) ? g_count[i] : 0;
    s[tid] = v;
    __syncthreads();
#pragma unroll
    for (int d = 1; d < 1024; d <<= 1) {
        int t = (tid >= d) ? s[tid - d] : 0;
        __syncthreads();
        s[tid] += t;
        __syncthreads();
    }
    if (i < N_NODES) g_csroff[i] = s[tid] - v;
    if (tid == 1023) g_bsum[blockIdx.x] = s[1023];
}

// phase 2+3 merged: each block redundantly scans the 98 block sums, then
// applies the prefix to its 256 csroff entries.
__global__ __launch_bounds__(256) void k_scan23() {
    __shared__ int wsum[4];
    __shared__ int ex[128];
    int tid = threadIdx.x, lane = tid & 31, wid = tid >> 5;
    int v = 0, x = 0;
    if (tid < 128) {
        v = (tid < NSCAN1) ? g_bsum[tid] : 0;
        x = v;
#pragma unroll
        for (int d = 1; d < 32; d <<= 1) {
            int t = __shfl_up_sync(0xffffffffu, x, d);
            if (lane >= d) x += t;
        }
        if (lane == 31) wsum[wid] = x;
    }
    __syncthreads();
    if (tid < 128) {
        int base = 0;
#pragma unroll
        for (int k = 0; k < 4; k++) base += (k < wid) ? wsum[k] : 0;
        ex[tid] = base + x - v;  // exclusive prefix of block sums
    }
    __syncthreads();
    int i = blockIdx.x * blockDim.x + tid;
    if (i < N_NODES) {
        int o = g_csroff[i] + ex[i >> 10];
        g_csroff[i] = o;
        g_cursor[i] = o;
    }
    if (i == 0) g_csroff[N_NODES] = N_EDGES;
}

__global__ void k_fill(const int* __restrict__ ei, const int* __restrict__ et) {
    int e = blockIdx.x * blockDim.x + threadIdx.x;
    if (e >= N_EDGES) return;
    int r = ei[e];
    int c = ei[N_EDGES + e];
    int t = et[e];
    int pos = atomicAdd(&g_cursor[c], 1);
    g_csrsrc[pos] = r;
    g_csrw0[pos] = g_rws[t] / fabsf(g_deg0[c]);
    g_csrw1[pos] = g_rws[NET + t] / fabsf(g_deg1[c]);
}

// ---------------- mma GEMM kernels (512 threads, 3 CTAs/SM) ----------------

// both input linears in ONE launch: blocks [0, nt0) do type 0, rest type 1
__global__ __launch_bounds__(512, 3) void k_mma_input(
    const float* __restrict__ x0, const float* __restrict__ x1,
    const int* __restrict__ lidx,
    const float* __restrict__ b0, const float* __restrict__ b1) {
    const int cnt0 = g_cnt[0], cnt1 = g_cnt[1];
    const int nt0 = (cnt0 + MTILE - 1) / MTILE;
    int pass, tile;
    if ((int)blockIdx.x < nt0) { pass = 0; tile = blockIdx.x; }
    else { pass = 1; tile = blockIdx.x - nt0; }
    const int cnt = pass ? cnt1 : cnt0;
    const int m0 = tile * MTILE;
    if (m0 >= cnt) return;
    const int* list = pass ? g_list1 : g_list0;
    const float* xk = pass ? x1 : x0;
    const float* b = pass ? b1 : b0;
    extern __shared__ char smem[];
    int tid = threadIdx.x;

    stage_b(smem, pass ? g_wI1 : g_wI0, tid);
    {
        int row = tid >> 3, oct = tid & 7;
        int lr = m0 + row;
        const float* src = nullptr;
        if (lr < cnt) src = xk + (size_t)lidx[list[lr]] * HID + oct * 16;
        stage_plain16(smem, row, oct, src);
    }
    __syncthreads();

    float acc[4][4] = {};
    mma_core(smem_u32(smem), acc);

    int lane = tid & 31, w = tid >> 5, wm = w & 1, wn = w >> 1;
#pragma unroll
    for (int mt = 0; mt < 2; mt++)
#pragma unroll
        for (int half = 0; half < 2; half++) {
            int lr = m0 + wm * 32 + mt * 16 + (lane >> 2) + half * 8;
            if (lr >= cnt) continue;
            float* dst = g_h + (size_t)list[lr] * HID;
#pragma unroll
            for (int nt = 0; nt < 2; nt++) {
                int c = wn * 16 + nt * 8 + (lane & 3) * 2;
                float2 bb = *(const float2*)(b + c);
                float2 o = {acc[mt * 2 + nt][half * 2 + 0] + bb.x,
                            acc[mt * 2 + nt][half * 2 + 1] + bb.y};
                *(float2*)(dst + c) = o;
            }
        }
}

// g_x = gather(h) @ conv0_w + b + g_h ; BN stats fused in epilogue
__global__ __launch_bounds__(512, 3) void k_mma_gemm0(const float* __restrict__ b) {
    const int m0 = blockIdx.x * MTILE;
    extern __shared__ char smem[];
    int tid = threadIdx.x;

    stage_b(smem, g_wC0, tid);
    stage_gather16(smem, tid >> 3, tid & 7, m0 + (tid >> 3), g_h, g_csrw0);
    __syncthreads();

    float acc[4][4] = {};
    mma_core(smem_u32(smem), acc);

    int lane = tid & 31, w = tid >> 5, wm = w & 1, wn = w >> 1;
    float s[2][2] = {}, s2[2][2] = {};
#pragma unroll
    for (int mt = 0; mt < 2; mt++)
#pragma unroll
        for (int half = 0; half < 2; half++) {
            int gr = m0 + wm * 32 + mt * 16 + (lane >> 2) + half * 8;
            if (gr >= N_NODES) continue;
            float* dst = g_x + (size_t)gr * HID;
            const float* hres = g_h + (size_t)gr * HID;
#pragma unroll
            for (int nt = 0; nt < 2; nt++) {
                int c = wn * 16 + nt * 8 + (lane & 3) * 2;
                float2 bb = *(const float2*)(b + c);
                float2 hv = *(const float2*)(hres + c);
                float2 o = {acc[mt * 2 + nt][half * 2 + 0] + bb.x + hv.x,
                            acc[mt * 2 + nt][half * 2 + 1] + bb.y + hv.y};
                *(float2*)(dst + c) = o;
                s[nt][0] += o.x;  s2[nt][0] += o.x * o.x;
                s[nt][1] += o.y;  s2[nt][1] += o.y * o.y;
            }
        }
#pragma unroll
    for (int d = 4; d < 32; d <<= 1)
#pragma unroll
        for (int nt = 0; nt < 2; nt++) {
            s[nt][0]  += __shfl_xor_sync(0xffffffffu, s[nt][0],  d);
            s[nt][1]  += __shfl_xor_sync(0xffffffffu, s[nt][1],  d);
            s2[nt][0] += __shfl_xor_sync(0xffffffffu, s2[nt][0], d);
            s2[nt][1] += __shfl_xor_sync(0xffffffffu, s2[nt][1], d);
        }
    if ((lane >> 2) == 0) {
#pragma unroll
        for (int nt = 0; nt < 2; nt++) {
            int c = wn * 16 + nt * 8 + (lane & 3) * 2;
            atomicAdd(&g_sum[c],       s[nt][0]);
            atomicAdd(&g_sum[c + 1],   s[nt][1]);
            atomicAdd(&g_sumsq[c],     s2[nt][0]);
            atomicAdd(&g_sumsq[c + 1], s2[nt][1]);
        }
    }
}

// out = gather(y) @ conv1_w + b, then log-softmax in the same kernel
__global__ __launch_bounds__(512, 3) void k_mma_gemm1(const float* __restrict__ b,
                                                      float* __restrict__ out) {
    const int m0 = blockIdx.x * MTILE;
    extern __shared__ char smem[];
    int tid = threadIdx.x;

    stage_gather16(smem, tid >> 3, tid & 7, m0 + (tid >> 3), g_h, g_csrw1);

    int lane = tid & 31, w = tid >> 5, wm = w & 1, wn = w >> 1;

    for (int ny = 0; ny < 3; ny++) {
        if (ny) __syncthreads();  // prior mma reads of B done
        stage_b(smem, g_wC1 + (size_t)ny * 16384, tid);
        __syncthreads();

        float acc[4][4] = {};
        mma_core(smem_u32(smem), acc);

        int n0 = ny * 128;
#pragma unroll
        for (int mt = 0; mt < 2; mt++)
#pragma unroll
            for (int half = 0; half < 2; half++) {
                int gr = m0 + wm * 32 + mt * 16 + (lane >> 2) + half * 8;
                if (gr >= N_NODES) continue;
                float* dst = out + (size_t)gr * OUTD;
#pragma unroll
                for (int nt = 0; nt < 2; nt++) {
                    int c = n0 + wn * 16 + nt * 8 + (lane & 3) * 2;
                    if (c < OUTD)
                        dst[c] = acc[mt * 2 + nt][half * 2 + 0] + b[c];
                    if (c + 1 < OUTD)
                        dst[c + 1] = acc[mt * 2 + nt][half * 2 + 1] + b[c + 1];
                }
            }
    }

    // ---- fused log-softmax over this CTA's 64 rows ----
    __syncthreads();
#pragma unroll
    for (int r4 = 0; r4 < 4; r4++) {
        int gr = m0 + w * 4 + r4;
        if (gr >= N_NODES) continue;
        float* row = out + (size_t)gr * OUTD;
        float v[11];
        float mx = -1e30f;
#pragma unroll
        for (int i = 0; i < 11; i++) {
            int c = lane + i * 32;
            v[i] = (c < OUTD) ? row[c] : -1e30f;
            mx = fmaxf(mx, v[i]);
        }
#pragma unroll
        for (int d = 16; d > 0; d >>= 1)
            mx = fmaxf(mx, __shfl_xor_sync(0xffffffffu, mx, d));
        float se = 0.f;
#pragma unroll
        for (int i = 0; i < 11; i++) se += __expf(v[i] - mx);
#pragma unroll
        for (int d = 16; d > 0; d >>= 1)
            se += __shfl_xor_sync(0xffffffffu, se, d);
        float lse = __logf(se) + mx;
#pragma unroll
        for (int i = 0; i < 11; i++) {
            int c = lane + i * 32;
            if (c < OUTD) row[c] = v[i] - lse;
        }
    }
}

// ---------------- BN (finalize + apply in one kernel) ----------------------
__global__ void k_bnapply(const float* __restrict__ gamma,
                          const float* __restrict__ beta,
                          const float* __restrict__ prelu_a) {
    __shared__ float ssc[HID], ssh[HID];
    if (threadIdx.x < HID) {
        int j = threadIdx.x;
        float mean = g_sum[j] / (float)N_NODES;
        float var = g_sumsq[j] / (float)N_NODES - mean * mean;
        float sc = gamma[j] * rsqrtf(var + BN_EPS);
        ssc[j] = sc;
        ssh[j] = beta[j] - mean * sc;
    }
    __syncthreads();
    const float a = __ldg(prelu_a);
    const int total = N_NODES * HID / 4;
    for (int i = blockIdx.x * blockDim.x + threadIdx.x; i < total;
         i += gridDim.x * blockDim.x) {
        int kk = i & 31;
        float4 x = ((const float4*)g_x)[i];
        float4 sc = ((const float4*)ssc)[kk];
        float4 sh = ((const float4*)ssh)[kk];
        float4 v;
        v.x = x.x * sc.x + sh.x;
        v.y = x.y * sc.y + sh.y;
        v.z = x.z * sc.z + sh.z;
        v.w = x.w * sc.w + sh.w;
        v.x = (v.x >= 0.f) ? v.x : a * v.x;
        v.y = (v.y >= 0.f) ? v.y : a * v.y;
        v.z = (v.z >= 0.f) ? v.z : a * v.z;
        v.w = (v.w >= 0.f) ? v.w : a * v.w;
        ((float4*)g_h)[i] = v;
    }
}

// ---------------- launch ---------------------------------------------------
extern "C" void kernel_launch(void* const* d_in, const int* in_sizes, int n_in,
                              void* d_out, int out_size) {
    const float* x0 = (const float*)d_in[0];
    const float* x1 = (const float*)d_in[1];
    const int* edge_index = (const int*)d_in[2];
    const int* edge_type = (const int*)d_in[3];
    const int* node_type = (const int*)d_in[4];
    const int* lidx = (const int*)d_in[5];
    const float* lin0_w = (const float*)d_in[6];
    const float* lin0_b = (const float*)d_in[7];
    const float* lin1_w = (const float*)d_in[8];
    const float* lin1_b = (const float*)d_in[9];
    const float* conv0_w = (const float*)d_in[10];
    const float* conv0_b = (const float*)d_in[11];
    const float* conv0_rw = (const float*)d_in[12];
    const float* conv1_w = (const float*)d_in[13];
    const float* conv1_b = (const float*)d_in[14];
    const float* conv1_rw = (const float*)d_in[15];
    const float* bn_g = (const float*)d_in[16];
    const float* bn_b = (const float*)d_in[17];
    const float* prelu_a = (const float*)d_in[18];
    float* out = (float*)d_out;

    cudaFuncSetAttribute(k_mma_input, cudaFuncAttributeMaxDynamicSharedMemorySize, SMEM_MMA);
    cudaFuncSetAttribute(k_mma_gemm0, cudaFuncAttributeMaxDynamicSharedMemorySize, SMEM_MMA);
    cudaFuncSetAttribute(k_mma_gemm1, cudaFuncAttributeMaxDynamicSharedMemorySize, SMEM_MMA);

    k_init<<<(N_NODES + 255) / 256, 256>>>(conv0_rw, conv1_rw,
                                           lin0_w, lin1_w, conv0_w, conv1_w);
    k_part_deg<<<(N_EDGES + 255) / 256, 256>>>(node_type, edge_index, edge_type);
    k_scan1<<<NSCAN1, 1024>>>();
    k_scan23<<<(N_NODES + 255) / 256, 256>>>();
    k_fill<<<(N_EDGES + 255) / 256, 256>>>(edge_index, edge_type);

    // both input linears in one launch (+2 slack blocks for tile split)
    k_mma_input<<<NTILES_M + 2, 512, SMEM_MMA>>>(x0, x1, lidx, lin0_b, lin1_b);

    // layer 0: gather fused into GEMM staging; BN stats fused in epilogue
    k_mma_gemm0<<<NTILES_M, 512, SMEM_MMA>>>(conv0_b);
    k_bnapply<<<2048, 256>>>(bn_g, bn_b, prelu_a);

    // layer 1: gather of y fused into GEMM staging + softmax
    k_mma_gemm1<<<NTILES_M, 512, SMEM_MMA>>>(conv1_b, out);
}

// round 17
// speedup vs baseline: 2.0681x; 1.1573x over previous
#include <cuda_runtime.h>
#include <cuda_fp16.h>
#include <cstdint>

#define N_NODES 100000
#define N_EDGES 500000
#define HID 128
#define OUTD 349
#define NET 8
#define BN_EPS 1e-5f
#define MTILE 64
#define NTILES_M ((N_NODES + MTILE - 1) / MTILE)  // 1563
#define NSCAN1 ((N_NODES + 1023) / 1024)          // 98

// ---------------- scratch (static device globals; no allocation) ----------
__device__ __half g_h[N_NODES * HID];    // input-linear output; later y = prelu(bn(x))  [fp16]
__device__ __half g_x[N_NODES * HID];    // conv0 out + residual (BN input)              [fp16]
__device__ float g_deg0[N_NODES], g_deg1[N_NODES];
__device__ int   g_count[N_NODES];
__device__ int   g_csroff[N_NODES + 1];
__device__ int   g_cursor[N_NODES];
__device__ int   g_bsum[NSCAN1];
__device__ int   g_csrsrc[N_EDGES];
__device__ float g_csrw0[N_EDGES], g_csrw1[N_EDGES];
__device__ float g_rws[2 * NET];
__device__ float g_sum[HID], g_sumsq[HID];
__device__ int   g_cnt[2];
__device__ int   g_list0[N_NODES], g_list1[N_NODES];

// fp16 weight images, layout [tile][k=128][n=128] row-major
__device__ __half g_wI0[16384];            // lin0_w
__device__ __half g_wI1[16384];            // lin1_w
__device__ __half g_wC0[16384];            // conv0_w
__device__ __half g_wC1[3 * 16384];        // conv1_w (3 tiles)

// ---------------- mma.sync GEMM machinery ----------------------------------
// A fp16, W fp16 (single term). 512 threads/CTA, 3 CTAs/SM.
#define ROWB 272                    // 136 fp16 padded row (conflict-free LDSM)
#define OFF_A   0                   // 64 x 272 = 17408
#define OFF_B   17408               // 128 x 272 = 34816
#define SMEM_MMA 52224              // 51KB -> 3 CTAs/SM

__device__ __forceinline__ uint32_t smem_u32(const void* p) {
    uint32_t a;
    asm("{ .reg .u64 t; cvta.to.shared.u64 t, %1; cvt.u32.u64 %0, t; }"
        : "=r"(a) : "l"(p));
    return a;
}

__device__ __forceinline__ void ldsm4(uint32_t addr, uint32_t* r) {
    asm volatile("ldmatrix.sync.aligned.m8n8.x4.shared.b16 {%0,%1,%2,%3}, [%4];"
                 : "=r"(r[0]), "=r"(r[1]), "=r"(r[2]), "=r"(r[3]) : "r"(addr));
}
__device__ __forceinline__ void ldsm2t(uint32_t addr, uint32_t* r) {
    asm volatile("ldmatrix.sync.aligned.m8n8.x2.trans.shared.b16 {%0,%1}, [%2];"
                 : "=r"(r[0]), "=r"(r[1]) : "r"(addr));
}
__device__ __forceinline__ void mma16816(float* d, const uint32_t* a, const uint32_t* b) {
    asm volatile(
        "mma.sync.aligned.m16n8k16.row.col.f32.f16.f16.f32 "
        "{%0,%1,%2,%3}, {%4,%5,%6,%7}, {%8,%9}, {%0,%1,%2,%3};"
        : "+f"(d[0]), "+f"(d[1]), "+f"(d[2]), "+f"(d[3])
        : "r"(a[0]), "r"(a[1]), "r"(a[2]), "r"(a[3]), "r"(b[0]), "r"(b[1]));
}

// write 16 fp32 (one eighth-row) as packed fp16 into the A tile
__device__ __forceinline__ void stage_write16(char* smem, int row, int oct,
                                              const float* a) {
    uint32_t off = (uint32_t)row * ROWB + oct * 32;
#pragma unroll
    for (int g = 0; g < 2; g++) {
        uint32_t p[4];
#pragma unroll
        for (int i = 0; i < 4; i++)
            asm("cvt.rn.f16x2.f32 %0, %1, %2;"
                : "=r"(p[i]) : "f"(a[g * 8 + 2 * i + 1]), "f"(a[g * 8 + 2 * i]));
        *reinterpret_cast<uint4*>(smem + OFF_A + off + g * 16) =
            make_uint4(p[0], p[1], p[2], p[3]);
    }
}

// stage 16 fp32 (eighth row) from a contiguous fp32 source row
__device__ __forceinline__ void stage_plain16(char* smem, int row, int oct,
                                              const float* src) {
    float f[16];
    if (src) {
#pragma unroll
        for (int g = 0; g < 4; g++) {
            float4 v = ((const float4*)src)[g];
            f[g * 4 + 0] = v.x; f[g * 4 + 1] = v.y;
            f[g * 4 + 2] = v.z; f[g * 4 + 3] = v.w;
        }
    } else {
#pragma unroll
        for (int i = 0; i < 16; i++) f[i] = 0.f;
    }
    stage_write16(smem, row, oct, f);
}

// gather-aggregate an eighth row over incoming edges; fp16 source rows
__device__ __forceinline__ void stage_gather16(char* smem, int row, int oct, int gr,
                                               const __half* srcbase,
                                               const float* warr) {
    float a[16];
#pragma unroll
    for (int i = 0; i < 16; i++) a[i] = 0.f;
    if (gr < N_NODES) {
        int s0 = g_csroff[gr], s1 = g_csroff[gr + 1];
#pragma unroll 2
        for (int e = s0; e < s1; e++) {
            int src = g_csrsrc[e];
            float w = warr[e];
            const uint4* p = (const uint4*)(srcbase + (size_t)src * HID + oct * 16);
#pragma unroll
            for (int g = 0; g < 2; g++) {
                uint4 u = __ldg(&p[g]);
                const __half2* hp = (const __half2*)&u;
#pragma unroll
                for (int j = 0; j < 4; j++) {
                    float2 f = __half22float2(hp[j]);
                    a[g * 8 + j * 2 + 0] += w * f.x;
                    a[g * 8 + j * 2 + 1] += w * f.y;
                }
            }
        }
    }
    stage_write16(smem, row, oct, a);
}

// copy one fp16 B tile ([k][n] image) into padded smem rows
__device__ __forceinline__ void stage_b(char* smem, const __half* bt, int tid) {
    const uint4* h4 = (const uint4*)bt;
    for (int i = tid; i < 2048; i += 512) {
        int k = i >> 4, s = i & 15;
        *(uint4*)(smem + OFF_B + k * ROWB + s * 16) = h4[i];
    }
}

// core: 16 warps; warp (wm=w&1, wn=w>>1 in 0..7): rows wm*32..+31, cols wn*16..+15
__device__ __forceinline__ void mma_core(uint32_t sb, float acc[4][4]) {
    int lane = threadIdx.x & 31;
    int w = threadIdx.x >> 5;
    int wm = w & 1, wn = w >> 1;
    uint32_t aaddr[2], baddr[2];
#pragma unroll
    for (int mt = 0; mt < 2; mt++)
        aaddr[mt] = sb + OFF_A +
                    (uint32_t)(wm * 32 + mt * 16 + (lane & 15)) * ROWB +
                    (lane >> 4) * 16;
#pragma unroll
    for (int nt = 0; nt < 2; nt++)
        baddr[nt] = sb + OFF_B + (uint32_t)(lane & 15) * ROWB +
                    (wn * 16 + nt * 8) * 2;
#pragma unroll
    for (int ks = 0; ks < 8; ks++) {
        uint32_t bh[2][2];
#pragma unroll
        for (int nt = 0; nt < 2; nt++)
            ldsm2t(baddr[nt] + ks * (16 * ROWB), bh[nt]);
#pragma unroll
        for (int mt = 0; mt < 2; mt++) {
            uint32_t ah[4];
            ldsm4(aaddr[mt] + ks * 32, ah);
#pragma unroll
            for (int nt = 0; nt < 2; nt++)
                mma16816(acc[mt * 2 + nt], ah, bh[nt]);
        }
    }
}

// ---------------- prep ----------------------------------------------------
__global__ void k_init(const float* __restrict__ rw0, const float* __restrict__ rw1,
                       const float* __restrict__ lin0_w,
                       const float* __restrict__ lin1_w,
                       const float* __restrict__ conv0_w,
                       const float* __restrict__ conv1_w) {
    int i = blockIdx.x * blockDim.x + threadIdx.x;
    if (i < N_NODES) { g_deg0[i] = 0.0f; g_deg1[i] = 0.0f; g_count[i] = 0; }
    if (i < HID)     { g_sum[i] = 0.0f;  g_sumsq[i] = 0.0f; }
    if (i < 2)       { g_cnt[i] = 0; }
    if (i < NET) {
        float v = rw0[i] * 100.0f;
        g_rws[i] = (v >= 0.0f) ? v : 0.01f * v;
    } else if (i < 2 * NET) {
        float v = rw1[i - NET] * 100.0f;
        g_rws[i] = (v >= 0.0f) ? v : 0.01f * v;
    }
    if (i < 6 * 16384) {
        int img = i >> 14;
        int rem = i & 16383;
        int k = rem >> 7, n = rem & 127;
        const float* W;
        int ncols, col, off;
        __half* hi;
        if (img == 0)      { W = lin0_w;  ncols = HID;  col = n; hi = g_wI0; off = rem; }
        else if (img == 1) { W = lin1_w;  ncols = HID;  col = n; hi = g_wI1; off = rem; }
        else if (img == 2) { W = conv0_w; ncols = HID;  col = n; hi = g_wC0; off = rem; }
        else { int t = img - 3; W = conv1_w; ncols = OUTD; col = t * 128 + n;
               hi = g_wC1; off = t * 16384 + rem; }
        float v = (col < ncols) ? W[(size_t)k * ncols + col] : 0.f;
        hi[off] = __float2half_rn(v);
    }
}

// partition (warp-aggregated) + degree/count accumulation in one launch
__global__ void k_part_deg(const int* __restrict__ ntype,
                           const int* __restrict__ ei,
                           const int* __restrict__ et) {
    int i = blockIdx.x * blockDim.x + threadIdx.x;
    int lane = threadIdx.x & 31;
    int t = (i < N_NODES) ? ntype[i] : -1;
#pragma unroll
    for (int tt = 0; tt < 2; tt++) {
        unsigned m = __ballot_sync(0xffffffffu, t == tt);
        if (t == tt) {
            int leader = __ffs(m) - 1;
            int pos = 0;
            if (lane == leader) pos = atomicAdd(&g_cnt[tt], __popc(m));
            pos = __shfl_sync(m, pos, leader);
            pos += __popc(m & ((1u << lane) - 1u));
            if (tt == 0) g_list0[pos] = i; else g_list1[pos] = i;
        }
    }
    if (i < N_EDGES) {
        int c = ei[N_EDGES + i];
        int ty = et[i];
        atomicAdd(&g_deg0[c], g_rws[ty]);
        atomicAdd(&g_deg1[c], g_rws[NET + ty]);
        atomicAdd(&g_count[c], 1);
    }
}

// phase 1 of scan: per-1024-block exclusive scan + block sums
__global__ __launch_bounds__(1024) void k_scan1() {
    __shared__ int s[1024];
    int tid = threadIdx.x;
    int i = blockIdx.x * 1024 + tid;
    int v = (i < N_NODES) ? g_count[i] : 0;
    s[tid] = v;
    __syncthreads();
#pragma unroll
    for (int d = 1; d < 1024; d <<= 1) {
        int t = (tid >= d) ? s[tid - d] : 0;
        __syncthreads();
        s[tid] += t;
        __syncthreads();
    }
    if (i < N_NODES) g_csroff[i] = s[tid] - v;
    if (tid == 1023) g_bsum[blockIdx.x] = s[1023];
}

// phase 2+3 merged
__global__ __launch_bounds__(256) void k_scan23() {
    __shared__ int wsum[4];
    __shared__ int ex[128];
    int tid = threadIdx.x, lane = tid & 31, wid = tid >> 5;
    int v = 0, x = 0;
    if (tid < 128) {
        v = (tid < NSCAN1) ? g_bsum[tid] : 0;
        x = v;
#pragma unroll
        for (int d = 1; d < 32; d <<= 1) {
            int t = __shfl_up_sync(0xffffffffu, x, d);
            if (lane >= d) x += t;
        }
        if (lane == 31) wsum[wid] = x;
    }
    __syncthreads();
    if (tid < 128) {
        int base = 0;
#pragma unroll
        for (int k = 0; k < 4; k++) base += (k < wid) ? wsum[k] : 0;
        ex[tid] = base + x - v;
    }
    __syncthreads();
    int i = blockIdx.x * blockDim.x + tid;
    if (i < N_NODES) {
        int o = g_csroff[i] + ex[i >> 10];
        g_csroff[i] = o;
        g_cursor[i] = o;
    }
    if (i == 0) g_csroff[N_NODES] = N_EDGES;
}

__global__ void k_fill(const int* __restrict__ ei, const int* __restrict__ et) {
    int e = blockIdx.x * blockDim.x + threadIdx.x;
    if (e >= N_EDGES) return;
    int r = ei[e];
    int c = ei[N_EDGES + e];
    int t = et[e];
    int pos = atomicAdd(&g_cursor[c], 1);
    g_csrsrc[pos] = r;
    g_csrw0[pos] = g_rws[t] / fabsf(g_deg0[c]);
    g_csrw1[pos] = g_rws[NET + t] / fabsf(g_deg1[c]);
}

// ---------------- mma GEMM kernels (512 threads, 3 CTAs/SM) ----------------

// both input linears in ONE launch: blocks [0, nt0) do type 0, rest type 1
__global__ __launch_bounds__(512, 3) void k_mma_input(
    const float* __restrict__ x0, const float* __restrict__ x1,
    const int* __restrict__ lidx,
    const float* __restrict__ b0, const float* __restrict__ b1) {
    const int cnt0 = g_cnt[0], cnt1 = g_cnt[1];
    const int nt0 = (cnt0 + MTILE - 1) / MTILE;
    int pass, tile;
    if ((int)blockIdx.x < nt0) { pass = 0; tile = blockIdx.x; }
    else { pass = 1; tile = blockIdx.x - nt0; }
    const int cnt = pass ? cnt1 : cnt0;
    const int m0 = tile * MTILE;
    if (m0 >= cnt) return;
    const int* list = pass ? g_list1 : g_list0;
    const float* xk = pass ? x1 : x0;
    const float* b = pass ? b1 : b0;
    extern __shared__ char smem[];
    int tid = threadIdx.x;

    stage_b(smem, pass ? g_wI1 : g_wI0, tid);
    {
        int row = tid >> 3, oct = tid & 7;
        int lr = m0 + row;
        const float* src = nullptr;
        if (lr < cnt) src = xk + (size_t)lidx[list[lr]] * HID + oct * 16;
        stage_plain16(smem, row, oct, src);
    }
    __syncthreads();

    float acc[4][4] = {};
    mma_core(smem_u32(smem), acc);

    int lane = tid & 31, w = tid >> 5, wm = w & 1, wn = w >> 1;
#pragma unroll
    for (int mt = 0; mt < 2; mt++)
#pragma unroll
        for (int half = 0; half < 2; half++) {
            int lr = m0 + wm * 32 + mt * 16 + (lane >> 2) + half * 8;
            if (lr >= cnt) continue;
            __half* dst = g_h + (size_t)list[lr] * HID;
#pragma unroll
            for (int nt = 0; nt < 2; nt++) {
                int c = wn * 16 + nt * 8 + (lane & 3) * 2;
                float2 bb = *(const float2*)(b + c);
                __half2 o = __floats2half2_rn(
                    acc[mt * 2 + nt][half * 2 + 0] + bb.x,
                    acc[mt * 2 + nt][half * 2 + 1] + bb.y);
                *(__half2*)(dst + c) = o;
            }
        }
}

// g_x = gather(h) @ conv0_w + b + g_h ; BN stats fused in epilogue
__global__ __launch_bounds__(512, 3) void k_mma_gemm0(const float* __restrict__ b) {
    const int m0 = blockIdx.x * MTILE;
    extern __shared__ char smem[];
    int tid = threadIdx.x;

    stage_b(smem, g_wC0, tid);
    stage_gather16(smem, tid >> 3, tid & 7, m0 + (tid >> 3), g_h, g_csrw0);
    __syncthreads();

    float acc[4][4] = {};
    mma_core(smem_u32(smem), acc);

    int lane = tid & 31, w = tid >> 5, wm = w & 1, wn = w >> 1;
    float s[2][2] = {}, s2[2][2] = {};
#pragma unroll
    for (int mt = 0; mt < 2; mt++)
#pragma unroll
        for (int half = 0; half < 2; half++) {
            int gr = m0 + wm * 32 + mt * 16 + (lane >> 2) + half * 8;
            if (gr >= N_NODES) continue;
            __half* dst = g_x + (size_t)gr * HID;
            const __half* hres = g_h + (size_t)gr * HID;
#pragma unroll
            for (int nt = 0; nt < 2; nt++) {
                int c = wn * 16 + nt * 8 + (lane & 3) * 2;
                float2 bb = *(const float2*)(b + c);
                float2 hv = __half22float2(*(const __half2*)(hres + c));
                float ox = acc[mt * 2 + nt][half * 2 + 0] + bb.x + hv.x;
                float oy = acc[mt * 2 + nt][half * 2 + 1] + bb.y + hv.y;
                *(__half2*)(dst + c) = __floats2half2_rn(ox, oy);
                s[nt][0] += ox;  s2[nt][0] += ox * ox;
                s[nt][1] += oy;  s2[nt][1] += oy * oy;
            }
        }
#pragma unroll
    for (int d = 4; d < 32; d <<= 1)
#pragma unroll
        for (int nt = 0; nt < 2; nt++) {
            s[nt][0]  += __shfl_xor_sync(0xffffffffu, s[nt][0],  d);
            s[nt][1]  += __shfl_xor_sync(0xffffffffu, s[nt][1],  d);
            s2[nt][0] += __shfl_xor_sync(0xffffffffu, s2[nt][0], d);
            s2[nt][1] += __shfl_xor_sync(0xffffffffu, s2[nt][1], d);
        }
    if ((lane >> 2) == 0) {
#pragma unroll
        for (int nt = 0; nt < 2; nt++) {
            int c = wn * 16 + nt * 8 + (lane & 3) * 2;
            atomicAdd(&g_sum[c],       s[nt][0]);
            atomicAdd(&g_sum[c + 1],   s[nt][1]);
            atomicAdd(&g_sumsq[c],     s2[nt][0]);
            atomicAdd(&g_sumsq[c + 1], s2[nt][1]);
        }
    }
}

// out = gather(y) @ conv1_w + b, then log-softmax in the same kernel
__global__ __launch_bounds__(512, 3) void k_mma_gemm1(const float* __restrict__ b,
                                                      float* __restrict__ out) {
    const int m0 = blockIdx.x * MTILE;
    extern __shared__ char smem[];
    int tid = threadIdx.x;

    stage_gather16(smem, tid >> 3, tid & 7, m0 + (tid >> 3), g_h, g_csrw1);

    int lane = tid & 31, w = tid >> 5, wm = w & 1, wn = w >> 1;

    for (int ny = 0; ny < 3; ny++) {
        if (ny) __syncthreads();  // prior mma reads of B done
        stage_b(smem, g_wC1 + (size_t)ny * 16384, tid);
        __syncthreads();

        float acc[4][4] = {};
        mma_core(smem_u32(smem), acc);

        int n0 = ny * 128;
#pragma unroll
        for (int mt = 0; mt < 2; mt++)
#pragma unroll
            for (int half = 0; half < 2; half++) {
                int gr = m0 + wm * 32 + mt * 16 + (lane >> 2) + half * 8;
                if (gr >= N_NODES) continue;
                float* dst = out + (size_t)gr * OUTD;
#pragma unroll
                for (int nt = 0; nt < 2; nt++) {
                    int c = n0 + wn * 16 + nt * 8 + (lane & 3) * 2;
                    if (c < OUTD)
                        dst[c] = acc[mt * 2 + nt][half * 2 + 0] + b[c];
                    if (c + 1 < OUTD)
                        dst[c + 1] = acc[mt * 2 + nt][half * 2 + 1] + b[c + 1];
                }
            }
    }

    // ---- fused log-softmax over this CTA's 64 rows ----
    __syncthreads();
#pragma unroll
    for (int r4 = 0; r4 < 4; r4++) {
        int gr = m0 + w * 4 + r4;
        if (gr >= N_NODES) continue;
        float* row = out + (size_t)gr * OUTD;
        float v[11];
        float mx = -1e30f;
#pragma unroll
        for (int i = 0; i < 11; i++) {
            int c = lane + i * 32;
            v[i] = (c < OUTD) ? row[c] : -1e30f;
            mx = fmaxf(mx, v[i]);
        }
#pragma unroll
        for (int d = 16; d > 0; d >>= 1)
            mx = fmaxf(mx, __shfl_xor_sync(0xffffffffu, mx, d));
        float se = 0.f;
#pragma unroll
        for (int i = 0; i < 11; i++) se += __expf(v[i] - mx);
#pragma unroll
        for (int d = 16; d > 0; d >>= 1)
            se += __shfl_xor_sync(0xffffffffu, se, d);
        float lse = __logf(se) + mx;
#pragma unroll
        for (int i = 0; i < 11; i++) {
            int c = lane + i * 32;
            if (c < OUTD) row[c] = v[i] - lse;
        }
    }
}

// ---------------- BN (finalize + apply in one kernel) ----------------------
__global__ void k_bnapply(const float* __restrict__ gamma,
                          const float* __restrict__ beta,
                          const float* __restrict__ prelu_a) {
    __shared__ float ssc[HID], ssh[HID];
    if (threadIdx.x < HID) {
        int j = threadIdx.x;
        float mean = g_sum[j] / (float)N_NODES;
        float var = g_sumsq[j] / (float)N_NODES - mean * mean;
        float sc = gamma[j] * rsqrtf(var + BN_EPS);
        ssc[j] = sc;
        ssh[j] = beta[j] - mean * sc;
    }
    __syncthreads();
    const float a = __ldg(prelu_a);
    const int total = N_NODES * HID / 8;  // uint4 = 8 halves
    for (int i = blockIdx.x * blockDim.x + threadIdx.x; i < total;
         i += gridDim.x * blockDim.x) {
        int cb = (i & 15) * 8;  // column base within row (HID/8 = 16 groups)
        uint4 u = ((const uint4*)g_x)[i];
        const __half2* hp = (const __half2*)&u;
        uint4 r;
        __half2* rp = (__half2*)&r;
#pragma unroll
        for (int j = 0; j < 4; j++) {
            float2 f = __half22float2(hp[j]);
            float scx = ssc[cb + j * 2], scy = ssc[cb + j * 2 + 1];
            float shx = ssh[cb + j * 2], shy = ssh[cb + j * 2 + 1];
            float vx = f.x * scx + shx;
            float vy = f.y * scy + shy;
            vx = (vx >= 0.f) ? vx : a * vx;
            vy = (vy >= 0.f) ? vy : a * vy;
            rp[j] = __floats2half2_rn(vx, vy);
        }
        ((uint4*)g_h)[i] = r;
    }
}

// ---------------- launch ---------------------------------------------------
extern "C" void kernel_launch(void* const* d_in, const int* in_sizes, int n_in,
                              void* d_out, int out_size) {
    const float* x0 = (const float*)d_in[0];
    const float* x1 = (const float*)d_in[1];
    const int* edge_index = (const int*)d_in[2];
    const int* edge_type = (const int*)d_in[3];
    const int* node_type = (const int*)d_in[4];
    const int* lidx = (const int*)d_in[5];
    const float* lin0_w = (const float*)d_in[6];
    const float* lin0_b = (const float*)d_in[7];
    const float* lin1_w = (const float*)d_in[8];
    const float* lin1_b = (const float*)d_in[9];
    const float* conv0_w = (const float*)d_in[10];
    const float* conv0_b = (const float*)d_in[11];
    const float* conv0_rw = (const float*)d_in[12];
    const float* conv1_w = (const float*)d_in[13];
    const float* conv1_b = (const float*)d_in[14];
    const float* conv1_rw = (const float*)d_in[15];
    const float* bn_g = (const float*)d_in[16];
    const float* bn_b = (const float*)d_in[17];
    const float* prelu_a = (const float*)d_in[18];
    float* out = (float*)d_out;

    cudaFuncSetAttribute(k_mma_input, cudaFuncAttributeMaxDynamicSharedMemorySize, SMEM_MMA);
    cudaFuncSetAttribute(k_mma_gemm0, cudaFuncAttributeMaxDynamicSharedMemorySize, SMEM_MMA);
    cudaFuncSetAttribute(k_mma_gemm1, cudaFuncAttributeMaxDynamicSharedMemorySize, SMEM_MMA);

    k_init<<<(N_NODES + 255) / 256, 256>>>(conv0_rw, conv1_rw,
                                           lin0_w, lin1_w, conv0_w, conv1_w);
    k_part_deg<<<(N_EDGES + 255) / 256, 256>>>(node_type, edge_index, edge_type);
    k_scan1<<<NSCAN1, 1024>>>();
    k_scan23<<<(N_NODES + 255) / 256, 256>>>();
    k_fill<<<(N_EDGES + 255) / 256, 256>>>(edge_index, edge_type);

    // both input linears in one launch (+2 slack blocks for tile split)
    k_mma_input<<<NTILES_M + 2, 512, SMEM_MMA>>>(x0, x1, lidx, lin0_b, lin1_b);

    // layer 0: gather fused into GEMM staging; BN stats fused in epilogue
    k_mma_gemm0<<<NTILES_M, 512, SMEM_MMA>>>(conv0_b);
    k_bnapply<<<2048, 256>>>(bn_g, bn_b, prelu_a);

    // layer 1: gather of y fused into GEMM staging + softmax
    k_mma_gemm1<<<NTILES_M, 512, SMEM_MMA>>>(conv1_b, out);
}